// round 2
// baseline (speedup 1.0000x reference)
#include <cuda_runtime.h>
#include <math.h>

// Problem constants
constexpr int SEQ  = 2048;
constexpr int DM   = 2048;
constexpr int NH   = 16;
constexpr int NKV  = 4;
constexpr int HD   = 128;
constexpr int WIN  = 1024;
constexpr float CLIPV = 8.0f;
constexpr float SCALE_F = 0.08838834764831845f; // 1/sqrt(128)

// Scratch (static device memory; no allocations allowed)
__device__ float g_q[SEQ * DM];          // 16 MB
__device__ float g_k[SEQ * NKV * HD];    // 4 MB
__device__ float g_v[SEQ * NKV * HD];    // 4 MB
__device__ float g_att[SEQ * DM];        // 16 MB

// ---------------------------------------------------------------------------
// Tiled fp32 GEMM: Y[M,N] = X[M,K] @ W[N,K]^T, optional clip.
// BM=BN=64, BK=16, 256 threads, 4x4 micro-tile per thread.
// ---------------------------------------------------------------------------
template <bool DO_CLIP>
__global__ void gemm_xwT(const float* __restrict__ X, const float* __restrict__ W,
                         float* __restrict__ Y, int K) {
    __shared__ float Xs[64][17];
    __shared__ float Ws[64][17];
    const int tid = threadIdx.x;
    const int tx = tid & 15, ty = tid >> 4;
    const int row0 = blockIdx.y << 6;
    const int col0 = blockIdx.x << 6;
    const int N = gridDim.x << 6;

    float acc[4][4] = {};

    for (int k0 = 0; k0 < K; k0 += 16) {
        #pragma unroll
        for (int idx = tid; idx < 1024; idx += 256) {
            int r = idx >> 4, c = idx & 15;
            Xs[r][c] = X[(row0 + r) * K + k0 + c];
            Ws[r][c] = W[(col0 + r) * K + k0 + c];
        }
        __syncthreads();
        #pragma unroll
        for (int kk = 0; kk < 16; kk++) {
            float a[4], b[4];
            #pragma unroll
            for (int i = 0; i < 4; i++) a[i] = Xs[ty * 4 + i][kk];
            #pragma unroll
            for (int j = 0; j < 4; j++) b[j] = Ws[tx * 4 + j][kk];
            #pragma unroll
            for (int i = 0; i < 4; i++)
                #pragma unroll
                for (int j = 0; j < 4; j++)
                    acc[i][j] = fmaf(a[i], b[j], acc[i][j]);
        }
        __syncthreads();
    }

    #pragma unroll
    for (int i = 0; i < 4; i++)
        #pragma unroll
        for (int j = 0; j < 4; j++) {
            float v = acc[i][j];
            if (DO_CLIP) v = fminf(fmaxf(v, -CLIPV), CLIPV);
            Y[(row0 + ty * 4 + i) * N + col0 + tx * 4 + j] = v;
        }
}

// ---------------------------------------------------------------------------
// Fused RMSNorm (per head, HD=128) + RoPE, in place.
// grid = (SEQ, nheads), block = 128 threads (one per dim).
// ---------------------------------------------------------------------------
__global__ void norm_rope_kernel(float* __restrict__ data, const float* __restrict__ w,
                                 int nheads) {
    const int s = blockIdx.x, h = blockIdx.y, d = threadIdx.x;
    float* row = data + (s * nheads + h) * HD;

    __shared__ float sh[HD];
    __shared__ float red[4];

    float x = row[d];
    float sq = x * x;
    #pragma unroll
    for (int o = 16; o; o >>= 1) sq += __shfl_xor_sync(0xffffffffu, sq, o);
    if ((d & 31) == 0) red[d >> 5] = sq;
    __syncthreads();

    float var = (red[0] + red[1] + red[2] + red[3]) * (1.0f / HD);
    float xn = x * rsqrtf(var + 1e-6f) * w[d];
    sh[d] = xn;
    __syncthreads();

    // RoPE: cos/sin of pos * theta^{-(d mod 64)/64}
    float inv_freq = powf(500000.0f, -(float)(d & 63) * (1.0f / 64.0f));
    float ang = (float)s * inv_freq;
    float sn, cs;
    sincosf(ang, &sn, &cs);
    float other = (d < 64) ? -sh[d + 64] : sh[d - 64];
    row[d] = xn * cs + other * sn;
}

// ---------------------------------------------------------------------------
// Flash-style windowed attention with sink column.
// grid = (SEQ/64, NH), 256 threads. One 64-query tile per block.
// K stored TRANSPOSED in smem (conflict-light logits reads); V read as float4.
// ---------------------------------------------------------------------------
constexpr int QLD = 130;  // Qs row stride  (64 rows x 128 dims)
constexpr int KLD = 68;   // Kt row stride  (128 dims x 64 keys, transposed)
constexpr int VLD = 132;  // Vs row stride  (64 keys x 128 dims), float4-aligned
constexpr int PLD = 68;   // Ps row stride  (64 q x 64 k probs)
constexpr int ATTN_SMEM_FLOATS = 64 * QLD + 128 * KLD + 64 * VLD + 64 * PLD;

__global__ void attn_kernel(const float* __restrict__ sinks) {
    extern __shared__ float smem[];
    float* Qs = smem;
    float* Kt = Qs + 64 * QLD;
    float* Vs = Kt + 128 * KLD;
    float* Ps = Vs + 64 * VLD;

    const int h = blockIdx.y;
    const int q0 = blockIdx.x << 6;
    const int kvh = h >> 2;             // N_REP = 4
    const int tid = threadIdx.x;
    const int tx = tid & 15, ty = tid >> 4;

    // Load Q tile
    for (int idx = tid; idx < 64 * HD; idx += 256) {
        int r = idx >> 7, c = idx & 127;
        Qs[r * QLD + c] = g_q[(q0 + r) * DM + h * HD + c];
    }

    float m[4], l[4], acc[4][8];
    #pragma unroll
    for (int i = 0; i < 4; i++) {
        m[i] = -1e30f;
        l[i] = 0.0f;
        #pragma unroll
        for (int c = 0; c < 8; c++) acc[i][c] = 0.0f;
    }

    int lo = q0 - WIN + 1;
    if (lo < 0) lo = 0;
    const int kt_lo = lo >> 6;
    const int kt_hi = (q0 + 63) >> 6;
    __syncthreads();

    for (int kt = kt_lo; kt <= kt_hi; kt++) {
        const int k0 = kt << 6;
        // Load K (transposed) and V tiles
        for (int idx = tid; idx < 64 * HD; idx += 256) {
            int r = idx >> 7, c = idx & 127;
            int gbase = (k0 + r) * (NKV * HD) + kvh * HD + c;
            Kt[c * KLD + r] = g_k[gbase];
            Vs[r * VLD + c] = g_v[gbase];
        }
        __syncthreads();

        // Logits 4x4 per thread
        float lg[4][4] = {};
        #pragma unroll 4
        for (int kk = 0; kk < HD; kk++) {
            float a[4], b[4];
            #pragma unroll
            for (int i = 0; i < 4; i++) a[i] = Qs[(ty * 4 + i) * QLD + kk];
            #pragma unroll
            for (int j = 0; j < 4; j++) b[j] = Kt[kk * KLD + tx * 4 + j];
            #pragma unroll
            for (int i = 0; i < 4; i++)
                #pragma unroll
                for (int j = 0; j < 4; j++)
                    lg[i][j] = fmaf(a[i], b[j], lg[i][j]);
        }

        // Mask + online softmax (row groups = 16 lanes sharing ty)
        #pragma unroll
        for (int i = 0; i < 4; i++) {
            const int qi = q0 + ty * 4 + i;
            #pragma unroll
            for (int j = 0; j < 4; j++) {
                const int ki = k0 + tx * 4 + j;
                lg[i][j] = (ki <= qi && ki > qi - WIN) ? lg[i][j] * SCALE_F : -1e30f;
            }
            float rm = fmaxf(fmaxf(lg[i][0], lg[i][1]), fmaxf(lg[i][2], lg[i][3]));
            #pragma unroll
            for (int msk = 8; msk; msk >>= 1)
                rm = fmaxf(rm, __shfl_xor_sync(0xffffffffu, rm, msk));
            const float nm = fmaxf(m[i], rm);
            const float sc = expf(m[i] - nm);
            float rs = 0.0f;
            #pragma unroll
            for (int j = 0; j < 4; j++) {
                float p = (lg[i][j] > -1e29f) ? expf(lg[i][j] - nm) : 0.0f;
                lg[i][j] = p;
                rs += p;
            }
            #pragma unroll
            for (int msk = 8; msk; msk >>= 1)
                rs += __shfl_xor_sync(0xffffffffu, rs, msk);
            l[i] = l[i] * sc + rs;
            m[i] = nm;
            #pragma unroll
            for (int c = 0; c < 8; c++) acc[i][c] *= sc;
            #pragma unroll
            for (int j = 0; j < 4; j++)
                Ps[(ty * 4 + i) * PLD + tx * 4 + j] = lg[i][j];
        }
        __syncthreads();

        // PV: out tile 64x128; thread owns rows ty*4..+3, cols tx*8..+7
        #pragma unroll 2
        for (int j = 0; j < 64; j++) {
            const float4* vp = reinterpret_cast<const float4*>(Vs + j * VLD + tx * 8);
            const float4 va = vp[0];
            const float4 vb = vp[1];
            #pragma unroll
            for (int i = 0; i < 4; i++) {
                const float p = Ps[(ty * 4 + i) * PLD + j];
                acc[i][0] = fmaf(p, va.x, acc[i][0]);
                acc[i][1] = fmaf(p, va.y, acc[i][1]);
                acc[i][2] = fmaf(p, va.z, acc[i][2]);
                acc[i][3] = fmaf(p, va.w, acc[i][3]);
                acc[i][4] = fmaf(p, vb.x, acc[i][4]);
                acc[i][5] = fmaf(p, vb.y, acc[i][5]);
                acc[i][6] = fmaf(p, vb.z, acc[i][6]);
                acc[i][7] = fmaf(p, vb.w, acc[i][7]);
            }
        }
        __syncthreads();
    }

    // Fold in sink column and write output
    const float snk = sinks[h];
    #pragma unroll
    for (int i = 0; i < 4; i++) {
        const float M = fmaxf(m[i], snk);
        const float denom = l[i] * expf(m[i] - M) + expf(snk - M);
        const float ns = expf(m[i] - M) / denom;
        const int qi = q0 + ty * 4 + i;
        #pragma unroll
        for (int c = 0; c < 8; c++)
            g_att[qi * DM + h * HD + tx * 8 + c] = acc[i][c] * ns;
    }
}

// ---------------------------------------------------------------------------
// Launch
// ---------------------------------------------------------------------------
extern "C" void kernel_launch(void* const* d_in, const int* in_sizes, int n_in,
                              void* d_out, int out_size) {
    const float* x     = (const float*)d_in[0];
    const float* w_q   = (const float*)d_in[1];
    const float* w_k   = (const float*)d_in[2];
    const float* w_v   = (const float*)d_in[3];
    const float* w_out = (const float*)d_in[4];
    const float* qnw   = (const float*)d_in[5];
    const float* knw   = (const float*)d_in[6];
    const float* sinks = (const float*)d_in[7];
    float* out = (float*)d_out;

    float *pq = nullptr, *pk = nullptr, *pv = nullptr, *pa = nullptr;
    cudaGetSymbolAddress((void**)&pq, g_q);
    cudaGetSymbolAddress((void**)&pk, g_k);
    cudaGetSymbolAddress((void**)&pv, g_v);
    cudaGetSymbolAddress((void**)&pa, g_att);

    const dim3 blk(256);

    // Projections with clip
    gemm_xwT<true><<<dim3(DM / 64, SEQ / 64), blk>>>(x, w_q, pq, DM);
    gemm_xwT<true><<<dim3((NKV * HD) / 64, SEQ / 64), blk>>>(x, w_k, pk, DM);
    gemm_xwT<true><<<dim3((NKV * HD) / 64, SEQ / 64), blk>>>(x, w_v, pv, DM);

    // RMSNorm + RoPE (in place) on q and k
    norm_rope_kernel<<<dim3(SEQ, NH), 128>>>(pq, qnw, NH);
    norm_rope_kernel<<<dim3(SEQ, NKV), 128>>>(pk, knw, NKV);

    // Windowed attention + sink softmax
    const int smem_bytes = ATTN_SMEM_FLOATS * (int)sizeof(float);
    cudaFuncSetAttribute(attn_kernel, cudaFuncAttributeMaxDynamicSharedMemorySize,
                         smem_bytes);
    attn_kernel<<<dim3(SEQ / 64, NH), blk, smem_bytes>>>(sinks);

    // Output projection (no clip)
    gemm_xwT<false><<<dim3(DM / 64, SEQ / 64), blk>>>(pa, w_out, out, DM);
}

// round 4
// speedup vs baseline: 1.5211x; 1.5211x over previous
#include <cuda_runtime.h>
#include <cuda_bf16.h>
#include <math.h>
#include <stdint.h>

// Problem constants
constexpr int SEQ  = 2048;
constexpr int DM   = 2048;
constexpr int NH   = 16;
constexpr int NKV  = 4;
constexpr int HD   = 128;
constexpr int WIN  = 1024;
constexpr int KVD  = NKV * HD;   // 512
constexpr float CLIPV = 8.0f;
constexpr float SCALE_F = 0.08838834764831845f; // 1/sqrt(128)

// ---------------------------------------------------------------------------
// Static scratch (no allocations allowed)
// ---------------------------------------------------------------------------
__device__ float g_q[SEQ * DM];          // 16 MB
__device__ float g_k[SEQ * KVD];         // 4 MB
__device__ float g_v[SEQ * KVD];         // 4 MB
__device__ float g_att[SEQ * DM];        // 16 MB

// Split-bf16 (hi/lo) copies for tensor-core GEMMs
__device__ __nv_bfloat16 g_xh[SEQ * DM],  g_xl[SEQ * DM];
__device__ __nv_bfloat16 g_wqh[DM * DM],  g_wql[DM * DM];
__device__ __nv_bfloat16 g_wkh[KVD * DM], g_wkl[KVD * DM];
__device__ __nv_bfloat16 g_wvh[KVD * DM], g_wvl[KVD * DM];
__device__ __nv_bfloat16 g_woh[DM * DM],  g_wol[DM * DM];
__device__ __nv_bfloat16 g_ah[SEQ * DM],  g_al[SEQ * DM];

// ---------------------------------------------------------------------------
// PTX helpers (sm_80+ instruction set only — ptxas here targets plain sm_103)
// ---------------------------------------------------------------------------
__device__ __forceinline__ uint32_t smem_u32(const void* p) {
    uint32_t a;
    asm("{ .reg .u64 t; cvta.to.shared.u64 t, %1; cvt.u32.u64 %0, t; }"
        : "=r"(a) : "l"(p));
    return a;
}

__device__ __forceinline__ void cp_async16(uint32_t sp, const void* gp) {
    asm volatile("cp.async.cg.shared.global [%0], [%1], 16;"
                 :: "r"(sp), "l"(gp) : "memory");
}
__device__ __forceinline__ void cp_commit() {
    asm volatile("cp.async.commit_group;" ::: "memory");
}
template <int N>
__device__ __forceinline__ void cp_wait() {
    asm volatile("cp.async.wait_group %0;" :: "n"(N) : "memory");
}

__device__ __forceinline__ void ldmatrix_x4(uint32_t* r, uint32_t addr) {
    asm volatile("ldmatrix.sync.aligned.m8n8.x4.shared.b16 {%0,%1,%2,%3}, [%4];"
                 : "=r"(r[0]), "=r"(r[1]), "=r"(r[2]), "=r"(r[3]) : "r"(addr));
}

__device__ __forceinline__ void mma_16816(float* c, const uint32_t* a, const uint32_t* b) {
    asm volatile(
        "mma.sync.aligned.m16n8k16.row.col.f32.bf16.bf16.f32 "
        "{%0,%1,%2,%3}, {%4,%5,%6,%7}, {%8,%9}, {%0,%1,%2,%3};"
        : "+f"(c[0]), "+f"(c[1]), "+f"(c[2]), "+f"(c[3])
        : "r"(a[0]), "r"(a[1]), "r"(a[2]), "r"(a[3]), "r"(b[0]), "r"(b[1]));
}

// ---------------------------------------------------------------------------
// Split fp32 -> (hi, lo) bf16
// ---------------------------------------------------------------------------
__global__ void split_kernel(const float* __restrict__ x,
                             __nv_bfloat16* __restrict__ hi,
                             __nv_bfloat16* __restrict__ lo, int n4) {
    int i = blockIdx.x * 256 + threadIdx.x;
    if (i >= n4) return;
    float4 v = ((const float4*)x)[i];
    __nv_bfloat16 h0 = __float2bfloat16(v.x);
    __nv_bfloat16 h1 = __float2bfloat16(v.y);
    __nv_bfloat16 h2 = __float2bfloat16(v.z);
    __nv_bfloat16 h3 = __float2bfloat16(v.w);
    __nv_bfloat16 l0 = __float2bfloat16(v.x - __bfloat162float(h0));
    __nv_bfloat16 l1 = __float2bfloat16(v.y - __bfloat162float(h1));
    __nv_bfloat16 l2 = __float2bfloat16(v.z - __bfloat162float(h2));
    __nv_bfloat16 l3 = __float2bfloat16(v.w - __bfloat162float(h3));
    __nv_bfloat162 hp0 = __halves2bfloat162(h0, h1);
    __nv_bfloat162 hp1 = __halves2bfloat162(h2, h3);
    __nv_bfloat162 lp0 = __halves2bfloat162(l0, l1);
    __nv_bfloat162 lp1 = __halves2bfloat162(l2, l3);
    uint2 hv, lv;
    hv.x = *(uint32_t*)&hp0; hv.y = *(uint32_t*)&hp1;
    lv.x = *(uint32_t*)&lp0; lv.y = *(uint32_t*)&lp1;
    ((uint2*)hi)[i] = hv;
    ((uint2*)lo)[i] = lv;
}

// ---------------------------------------------------------------------------
// mma.sync bf16 split GEMM: Y[M,N] = A[M,K] @ B[N,K]^T, 3 passes
// (Ah*Bh + Ah*Bl + Al*Bh), fp32 accumulators in registers.
// Block 128x128, BK=32, 3-stage cp.async pipeline, 256 threads (8 warps),
// warp tile 64x32 (4 m-tiles x 4 n-tiles of m16n8k16).
// ---------------------------------------------------------------------------
constexpr int LDSROW = 40;                       // padded row stride (bf16 elems)
constexpr int TILE_B = 128 * LDSROW * 2;         // 10240 bytes per tile
constexpr int STAGES = 3;
constexpr int GEMM_SMEM = STAGES * 2 * TILE_B;   // 61440 bytes

template <bool DO_CLIP>
__global__ __launch_bounds__(256, 1) void tc_gemm(
    const __nv_bfloat16* __restrict__ Ah, const __nv_bfloat16* __restrict__ Al,
    const __nv_bfloat16* __restrict__ Bh, const __nv_bfloat16* __restrict__ Bl,
    float* __restrict__ Y, int K, int N) {
    extern __shared__ char dsm[];
    const uint32_t sm0 = smem_u32(dsm);

    const int tid = threadIdx.x;
    const int wid = tid >> 5;
    const int lane = tid & 31;
    const int warp_m = wid & 1;         // 2 warps over M
    const int warp_n = wid >> 1;        // 4 warps over N
    const int row0 = blockIdx.y << 7;
    const int col0 = blockIdx.x << 7;

    const int NC = K >> 5;              // K-chunks per pass
    const int tot = NC * 3;

    float acc[4][4][4];
    #pragma unroll
    for (int i = 0; i < 4; i++)
        #pragma unroll
        for (int j = 0; j < 4; j++)
            #pragma unroll
            for (int t = 0; t < 4; t++) acc[i][j][t] = 0.0f;

    // load one chunk (A 128x32 + B 128x32 bf16) into stage s
    auto load_chunk = [&](int c, int s) {
        const int pass = c / NC;
        const int kc = c - pass * NC;
        const int k0 = kc << 5;
        const __nv_bfloat16* As = (pass == 2) ? Al : Ah;
        const __nv_bfloat16* Bs = (pass == 1) ? Bl : Bh;
        const uint32_t sa = sm0 + s * TILE_B;
        const uint32_t sb = sm0 + (STAGES + s) * TILE_B;
        #pragma unroll
        for (int t = 0; t < 2; t++) {
            int idx = tid + t * 256;
            int r = idx >> 2, g = idx & 3;
            cp_async16(sa + (uint32_t)(r * LDSROW + g * 8) * 2,
                       As + (size_t)(row0 + r) * K + k0 + g * 8);
        }
        #pragma unroll
        for (int t = 0; t < 2; t++) {
            int idx = tid + t * 256;
            int r = idx >> 2, g = idx & 3;
            cp_async16(sb + (uint32_t)(r * LDSROW + g * 8) * 2,
                       Bs + (size_t)(col0 + r) * K + k0 + g * 8);
        }
    };

    // prologue: stages 0..STAGES-2
    #pragma unroll
    for (int s = 0; s < STAGES - 1; s++) {
        load_chunk(s, s);
        cp_commit();
    }

    for (int c = 0; c < tot; c++) {
        if (c + STAGES - 1 < tot) load_chunk(c + STAGES - 1, (c + STAGES - 1) % STAGES);
        cp_commit();
        cp_wait<STAGES - 2>();
        __syncthreads();

        const int s = c % STAGES;
        const uint32_t abase = sm0 + s * TILE_B;
        const uint32_t bbase = sm0 + (STAGES + s) * TILE_B;

        #pragma unroll
        for (int ks = 0; ks < 2; ks++) {
            const int kc = ks * 16;
            uint32_t a_frag[4][4], b_frag[4][2];
            // A: 4 m-tiles of 16x16
            #pragma unroll
            for (int im = 0; im < 4; im++) {
                int row = warp_m * 64 + im * 16 + (lane & 15);
                int col = kc + ((lane >> 4) << 3);
                ldmatrix_x4(a_frag[im], abase + (uint32_t)(row * LDSROW + col) * 2);
            }
            // B: 2 x ldmatrix.x4, each covering two 8-col n-tiles
            #pragma unroll
            for (int ib = 0; ib < 2; ib++) {
                int n = warp_n * 32 + ib * 16 + (lane & 7) + ((lane >> 4) << 3);
                int col = kc + (lane & 8);
                uint32_t r4[4];
                ldmatrix_x4(r4, bbase + (uint32_t)(n * LDSROW + col) * 2);
                b_frag[ib * 2][0]     = r4[0]; b_frag[ib * 2][1]     = r4[1];
                b_frag[ib * 2 + 1][0] = r4[2]; b_frag[ib * 2 + 1][1] = r4[3];
            }
            #pragma unroll
            for (int im = 0; im < 4; im++)
                #pragma unroll
                for (int in = 0; in < 4; in++)
                    mma_16816(acc[im][in], a_frag[im], b_frag[in]);
        }
        __syncthreads();
    }

    // Epilogue: c0,c1 at (row, col..col+1); c2,c3 at (row+8, ...)
    #pragma unroll
    for (int im = 0; im < 4; im++) {
        const int row = row0 + warp_m * 64 + im * 16 + (lane >> 2);
        #pragma unroll
        for (int in = 0; in < 4; in++) {
            const int col = col0 + warp_n * 32 + in * 8 + 2 * (lane & 3);
            float2 v0 = make_float2(acc[im][in][0], acc[im][in][1]);
            float2 v1 = make_float2(acc[im][in][2], acc[im][in][3]);
            if (DO_CLIP) {
                v0.x = fminf(fmaxf(v0.x, -CLIPV), CLIPV);
                v0.y = fminf(fmaxf(v0.y, -CLIPV), CLIPV);
                v1.x = fminf(fmaxf(v1.x, -CLIPV), CLIPV);
                v1.y = fminf(fmaxf(v1.y, -CLIPV), CLIPV);
            }
            *(float2*)(Y + (size_t)row * N + col) = v0;
            *(float2*)(Y + (size_t)(row + 8) * N + col) = v1;
        }
    }
}

// ---------------------------------------------------------------------------
// Fused RMSNorm (per head, HD=128) + RoPE, in place.
// ---------------------------------------------------------------------------
__global__ void norm_rope_kernel(float* __restrict__ data, const float* __restrict__ w,
                                 int nheads) {
    const int s = blockIdx.x, h = blockIdx.y, d = threadIdx.x;
    float* row = data + (s * nheads + h) * HD;

    __shared__ float sh[HD];
    __shared__ float red[4];

    float x = row[d];
    float sq = x * x;
    #pragma unroll
    for (int o = 16; o; o >>= 1) sq += __shfl_xor_sync(0xffffffffu, sq, o);
    if ((d & 31) == 0) red[d >> 5] = sq;
    __syncthreads();

    float var = (red[0] + red[1] + red[2] + red[3]) * (1.0f / HD);
    float xn = x * rsqrtf(var + 1e-6f) * w[d];
    sh[d] = xn;
    __syncthreads();

    float inv_freq = powf(500000.0f, -(float)(d & 63) * (1.0f / 64.0f));
    float ang = (float)s * inv_freq;
    float sn, cs;
    sincosf(ang, &sn, &cs);
    float other = (d < 64) ? -sh[d + 64] : sh[d - 64];
    row[d] = xn * cs + other * sn;
}

// ---------------------------------------------------------------------------
// Flash-style windowed attention with sink column (fp32).
// ---------------------------------------------------------------------------
constexpr int QLD = 130;
constexpr int KLD = 68;
constexpr int VLD = 132;
constexpr int PLD = 68;
constexpr int ATTN_SMEM_FLOATS = 64 * QLD + 128 * KLD + 64 * VLD + 64 * PLD;

__global__ void attn_kernel(const float* __restrict__ sinks) {
    extern __shared__ float smem[];
    float* Qs = smem;
    float* Kt = Qs + 64 * QLD;
    float* Vs = Kt + 128 * KLD;
    float* Ps = Vs + 64 * VLD;

    const int h = blockIdx.y;
    const int q0 = blockIdx.x << 6;
    const int kvh = h >> 2;
    const int tid = threadIdx.x;
    const int tx = tid & 15, ty = tid >> 4;

    for (int idx = tid; idx < 64 * HD; idx += 256) {
        int r = idx >> 7, c = idx & 127;
        Qs[r * QLD + c] = g_q[(q0 + r) * DM + h * HD + c];
    }

    float m[4], l[4], acc[4][8];
    #pragma unroll
    for (int i = 0; i < 4; i++) {
        m[i] = -1e30f;
        l[i] = 0.0f;
        #pragma unroll
        for (int c = 0; c < 8; c++) acc[i][c] = 0.0f;
    }

    int lo = q0 - WIN + 1;
    if (lo < 0) lo = 0;
    const int kt_lo = lo >> 6;
    const int kt_hi = (q0 + 63) >> 6;
    __syncthreads();

    for (int kt = kt_lo; kt <= kt_hi; kt++) {
        const int k0 = kt << 6;
        for (int idx = tid; idx < 64 * HD; idx += 256) {
            int r = idx >> 7, c = idx & 127;
            int gbase = (k0 + r) * KVD + kvh * HD + c;
            Kt[c * KLD + r] = g_k[gbase];
            Vs[r * VLD + c] = g_v[gbase];
        }
        __syncthreads();

        float lg[4][4] = {};
        #pragma unroll 4
        for (int kk = 0; kk < HD; kk++) {
            float a[4], b[4];
            #pragma unroll
            for (int i = 0; i < 4; i++) a[i] = Qs[(ty * 4 + i) * QLD + kk];
            #pragma unroll
            for (int j = 0; j < 4; j++) b[j] = Kt[kk * KLD + tx * 4 + j];
            #pragma unroll
            for (int i = 0; i < 4; i++)
                #pragma unroll
                for (int j = 0; j < 4; j++)
                    lg[i][j] = fmaf(a[i], b[j], lg[i][j]);
        }

        #pragma unroll
        for (int i = 0; i < 4; i++) {
            const int qi = q0 + ty * 4 + i;
            #pragma unroll
            for (int j = 0; j < 4; j++) {
                const int ki = k0 + tx * 4 + j;
                lg[i][j] = (ki <= qi && ki > qi - WIN) ? lg[i][j] * SCALE_F : -1e30f;
            }
            float rm = fmaxf(fmaxf(lg[i][0], lg[i][1]), fmaxf(lg[i][2], lg[i][3]));
            #pragma unroll
            for (int msk = 8; msk; msk >>= 1)
                rm = fmaxf(rm, __shfl_xor_sync(0xffffffffu, rm, msk));
            const float nm = fmaxf(m[i], rm);
            const float sc = expf(m[i] - nm);
            float rs = 0.0f;
            #pragma unroll
            for (int j = 0; j < 4; j++) {
                float p = (lg[i][j] > -1e29f) ? expf(lg[i][j] - nm) : 0.0f;
                lg[i][j] = p;
                rs += p;
            }
            #pragma unroll
            for (int msk = 8; msk; msk >>= 1)
                rs += __shfl_xor_sync(0xffffffffu, rs, msk);
            l[i] = l[i] * sc + rs;
            m[i] = nm;
            #pragma unroll
            for (int c = 0; c < 8; c++) acc[i][c] *= sc;
            #pragma unroll
            for (int j = 0; j < 4; j++)
                Ps[(ty * 4 + i) * PLD + tx * 4 + j] = lg[i][j];
        }
        __syncthreads();

        #pragma unroll 2
        for (int j = 0; j < 64; j++) {
            const float4* vp = reinterpret_cast<const float4*>(Vs + j * VLD + tx * 8);
            const float4 va = vp[0];
            const float4 vb = vp[1];
            #pragma unroll
            for (int i = 0; i < 4; i++) {
                const float p = Ps[(ty * 4 + i) * PLD + j];
                acc[i][0] = fmaf(p, va.x, acc[i][0]);
                acc[i][1] = fmaf(p, va.y, acc[i][1]);
                acc[i][2] = fmaf(p, va.z, acc[i][2]);
                acc[i][3] = fmaf(p, va.w, acc[i][3]);
                acc[i][4] = fmaf(p, vb.x, acc[i][4]);
                acc[i][5] = fmaf(p, vb.y, acc[i][5]);
                acc[i][6] = fmaf(p, vb.z, acc[i][6]);
                acc[i][7] = fmaf(p, vb.w, acc[i][7]);
            }
        }
        __syncthreads();
    }

    const float snk = sinks[h];
    #pragma unroll
    for (int i = 0; i < 4; i++) {
        const float M = fmaxf(m[i], snk);
        const float denom = l[i] * expf(m[i] - M) + expf(snk - M);
        const float ns = expf(m[i] - M) / denom;
        const int qi = q0 + ty * 4 + i;
        #pragma unroll
        for (int c = 0; c < 8; c++)
            g_att[qi * DM + h * HD + tx * 8 + c] = acc[i][c] * ns;
    }
}

// ---------------------------------------------------------------------------
// Launch
// ---------------------------------------------------------------------------
extern "C" void kernel_launch(void* const* d_in, const int* in_sizes, int n_in,
                              void* d_out, int out_size) {
    const float* x     = (const float*)d_in[0];
    const float* w_q   = (const float*)d_in[1];
    const float* w_k   = (const float*)d_in[2];
    const float* w_v   = (const float*)d_in[3];
    const float* w_out = (const float*)d_in[4];
    const float* qnw   = (const float*)d_in[5];
    const float* knw   = (const float*)d_in[6];
    const float* sinks = (const float*)d_in[7];
    float* out = (float*)d_out;

    float *pq, *pk, *pv, *pa;
    cudaGetSymbolAddress((void**)&pq, g_q);
    cudaGetSymbolAddress((void**)&pk, g_k);
    cudaGetSymbolAddress((void**)&pv, g_v);
    cudaGetSymbolAddress((void**)&pa, g_att);

    __nv_bfloat16 *xh, *xl, *wqh, *wql, *wkh, *wkl, *wvh, *wvl, *woh, *wol, *ah, *al;
    cudaGetSymbolAddress((void**)&xh,  g_xh);  cudaGetSymbolAddress((void**)&xl,  g_xl);
    cudaGetSymbolAddress((void**)&wqh, g_wqh); cudaGetSymbolAddress((void**)&wql, g_wql);
    cudaGetSymbolAddress((void**)&wkh, g_wkh); cudaGetSymbolAddress((void**)&wkl, g_wkl);
    cudaGetSymbolAddress((void**)&wvh, g_wvh); cudaGetSymbolAddress((void**)&wvl, g_wvl);
    cudaGetSymbolAddress((void**)&woh, g_woh); cudaGetSymbolAddress((void**)&wol, g_wol);
    cudaGetSymbolAddress((void**)&ah,  g_ah);  cudaGetSymbolAddress((void**)&al,  g_al);

    auto split = [&](const float* src, __nv_bfloat16* h, __nv_bfloat16* l, int n) {
        int n4 = n >> 2;
        split_kernel<<<(n4 + 255) / 256, 256>>>(src, h, l, n4);
    };
    split(x,     xh,  xl,  SEQ * DM);
    split(w_q,   wqh, wql, DM * DM);
    split(w_k,   wkh, wkl, KVD * DM);
    split(w_v,   wvh, wvl, KVD * DM);
    split(w_out, woh, wol, DM * DM);

    cudaFuncSetAttribute(tc_gemm<true>,  cudaFuncAttributeMaxDynamicSharedMemorySize, GEMM_SMEM);
    cudaFuncSetAttribute(tc_gemm<false>, cudaFuncAttributeMaxDynamicSharedMemorySize, GEMM_SMEM);

    // Projections (mma.sync bf16, split x3, clip in epilogue)
    tc_gemm<true><<<dim3(DM / 128, SEQ / 128), 256, GEMM_SMEM>>>(xh, xl, wqh, wql, pq, DM, DM);
    tc_gemm<true><<<dim3(KVD / 128, SEQ / 128), 256, GEMM_SMEM>>>(xh, xl, wkh, wkl, pk, DM, KVD);
    tc_gemm<true><<<dim3(KVD / 128, SEQ / 128), 256, GEMM_SMEM>>>(xh, xl, wvh, wvl, pv, DM, KVD);

    // RMSNorm + RoPE (in place)
    norm_rope_kernel<<<dim3(SEQ, NH), 128>>>(pq, qnw, NH);
    norm_rope_kernel<<<dim3(SEQ, NKV), 128>>>(pk, knw, NKV);

    // Windowed attention + sink softmax (fp32)
    const int attn_smem = ATTN_SMEM_FLOATS * (int)sizeof(float);
    cudaFuncSetAttribute(attn_kernel, cudaFuncAttributeMaxDynamicSharedMemorySize, attn_smem);
    attn_kernel<<<dim3(SEQ / 64, NH), 256, attn_smem>>>(sinks);

    // Output projection (mma.sync bf16, split x3)
    split(pa, ah, al, SEQ * DM);
    tc_gemm<false><<<dim3(DM / 128, SEQ / 128), 256, GEMM_SMEM>>>(ah, al, woh, wol, out, DM, DM);
}

// round 8
// speedup vs baseline: 2.1019x; 1.3819x over previous
#include <cuda_runtime.h>
#include <cuda_bf16.h>
#include <math.h>
#include <stdint.h>

// Problem constants
constexpr int SEQ  = 2048;
constexpr int DM   = 2048;
constexpr int NH   = 16;
constexpr int NKV  = 4;
constexpr int HD   = 128;
constexpr int WIN  = 1024;
constexpr int KVD  = NKV * HD;   // 512
constexpr float CLIPV = 8.0f;
constexpr float SCALE_F = 0.08838834764831845f; // 1/sqrt(128)

// ---------------------------------------------------------------------------
// Static scratch (no allocations allowed)
// ---------------------------------------------------------------------------
__device__ float g_q[SEQ * DM];          // fp32 q projection
__device__ float g_k[SEQ * KVD];
__device__ float g_v[SEQ * KVD];

// Split-bf16 (hi/lo) buffers
__device__ __nv_bfloat16 g_xh[SEQ * DM],  g_xl[SEQ * DM];
__device__ __nv_bfloat16 g_wqh[DM * DM],  g_wql[DM * DM];
__device__ __nv_bfloat16 g_wkh[KVD * DM], g_wkl[KVD * DM];
__device__ __nv_bfloat16 g_wvh[KVD * DM], g_wvl[KVD * DM];
__device__ __nv_bfloat16 g_woh[DM * DM],  g_wol[DM * DM];
__device__ __nv_bfloat16 g_ah[SEQ * DM],  g_al[SEQ * DM];      // attention out hi/lo
__device__ __nv_bfloat16 g_qnh[SEQ * DM], g_qnl[SEQ * DM];     // normed+roped q hi/lo
__device__ __nv_bfloat16 g_knh[SEQ * KVD], g_knl[SEQ * KVD];   // normed+roped k hi/lo
__device__ __nv_bfloat16 g_vnh[SEQ * KVD], g_vnl[SEQ * KVD];   // v hi/lo

// ---------------------------------------------------------------------------
// PTX helpers (sm_80+ instruction set — ptxas here targets plain sm_103)
// ---------------------------------------------------------------------------
__device__ __forceinline__ uint32_t smem_u32(const void* p) {
    uint32_t a;
    asm("{ .reg .u64 t; cvta.to.shared.u64 t, %1; cvt.u32.u64 %0, t; }"
        : "=r"(a) : "l"(p));
    return a;
}

__device__ __forceinline__ void cp_async16(uint32_t sp, const void* gp) {
    asm volatile("cp.async.cg.shared.global [%0], [%1], 16;"
                 :: "r"(sp), "l"(gp) : "memory");
}
__device__ __forceinline__ void cp_commit() {
    asm volatile("cp.async.commit_group;" ::: "memory");
}
template <int N>
__device__ __forceinline__ void cp_wait() {
    asm volatile("cp.async.wait_group %0;" :: "n"(N) : "memory");
}

__device__ __forceinline__ void ldmatrix_x4(uint32_t* r, uint32_t addr) {
    asm volatile("ldmatrix.sync.aligned.m8n8.x4.shared.b16 {%0,%1,%2,%3}, [%4];"
                 : "=r"(r[0]), "=r"(r[1]), "=r"(r[2]), "=r"(r[3]) : "r"(addr));
}
__device__ __forceinline__ void ldmatrix_x4_trans(uint32_t* r, uint32_t addr) {
    asm volatile("ldmatrix.sync.aligned.m8n8.x4.trans.shared.b16 {%0,%1,%2,%3}, [%4];"
                 : "=r"(r[0]), "=r"(r[1]), "=r"(r[2]), "=r"(r[3]) : "r"(addr));
}

__device__ __forceinline__ void mma_16816(float* c, const uint32_t* a, const uint32_t* b) {
    asm volatile(
        "mma.sync.aligned.m16n8k16.row.col.f32.bf16.bf16.f32 "
        "{%0,%1,%2,%3}, {%4,%5,%6,%7}, {%8,%9}, {%0,%1,%2,%3};"
        : "+f"(c[0]), "+f"(c[1]), "+f"(c[2]), "+f"(c[3])
        : "r"(a[0]), "r"(a[1]), "r"(a[2]), "r"(a[3]), "r"(b[0]), "r"(b[1]));
}

// ---------------------------------------------------------------------------
// Split fp32 -> (hi, lo) bf16
// ---------------------------------------------------------------------------
__global__ void split_kernel(const float* __restrict__ x,
                             __nv_bfloat16* __restrict__ hi,
                             __nv_bfloat16* __restrict__ lo, int n4) {
    int i = blockIdx.x * 256 + threadIdx.x;
    if (i >= n4) return;
    float4 v = ((const float4*)x)[i];
    __nv_bfloat16 h0 = __float2bfloat16(v.x);
    __nv_bfloat16 h1 = __float2bfloat16(v.y);
    __nv_bfloat16 h2 = __float2bfloat16(v.z);
    __nv_bfloat16 h3 = __float2bfloat16(v.w);
    __nv_bfloat16 l0 = __float2bfloat16(v.x - __bfloat162float(h0));
    __nv_bfloat16 l1 = __float2bfloat16(v.y - __bfloat162float(h1));
    __nv_bfloat16 l2 = __float2bfloat16(v.z - __bfloat162float(h2));
    __nv_bfloat16 l3 = __float2bfloat16(v.w - __bfloat162float(h3));
    __nv_bfloat162 hp0 = __halves2bfloat162(h0, h1);
    __nv_bfloat162 hp1 = __halves2bfloat162(h2, h3);
    __nv_bfloat162 lp0 = __halves2bfloat162(l0, l1);
    __nv_bfloat162 lp1 = __halves2bfloat162(l2, l3);
    uint2 hv, lv;
    hv.x = *(uint32_t*)&hp0; hv.y = *(uint32_t*)&hp1;
    lv.x = *(uint32_t*)&lp0; lv.y = *(uint32_t*)&lp1;
    ((uint2*)hi)[i] = hv;
    ((uint2*)lo)[i] = lv;
}

// ---------------------------------------------------------------------------
// mma.sync bf16 split GEMM (unchanged from R3): Y = A @ B^T, 3 passes.
// ---------------------------------------------------------------------------
constexpr int LDSROW = 40;
constexpr int TILE_B = 128 * LDSROW * 2;
constexpr int STAGES = 3;
constexpr int GEMM_SMEM = STAGES * 2 * TILE_B;

template <bool DO_CLIP>
__global__ __launch_bounds__(256, 1) void tc_gemm(
    const __nv_bfloat16* __restrict__ Ah, const __nv_bfloat16* __restrict__ Al,
    const __nv_bfloat16* __restrict__ Bh, const __nv_bfloat16* __restrict__ Bl,
    float* __restrict__ Y, int K, int N) {
    extern __shared__ char dsm[];
    const uint32_t sm0 = smem_u32(dsm);

    const int tid = threadIdx.x;
    const int wid = tid >> 5;
    const int lane = tid & 31;
    const int warp_m = wid & 1;
    const int warp_n = wid >> 1;
    const int row0 = blockIdx.y << 7;
    const int col0 = blockIdx.x << 7;

    const int NC = K >> 5;
    const int tot = NC * 3;

    float acc[4][4][4];
    #pragma unroll
    for (int i = 0; i < 4; i++)
        #pragma unroll
        for (int j = 0; j < 4; j++)
            #pragma unroll
            for (int t = 0; t < 4; t++) acc[i][j][t] = 0.0f;

    auto load_chunk = [&](int c, int s) {
        const int pass = c / NC;
        const int kc = c - pass * NC;
        const int k0 = kc << 5;
        const __nv_bfloat16* As = (pass == 2) ? Al : Ah;
        const __nv_bfloat16* Bs = (pass == 1) ? Bl : Bh;
        const uint32_t sa = sm0 + s * TILE_B;
        const uint32_t sb = sm0 + (STAGES + s) * TILE_B;
        #pragma unroll
        for (int t = 0; t < 2; t++) {
            int idx = tid + t * 256;
            int r = idx >> 2, g = idx & 3;
            cp_async16(sa + (uint32_t)(r * LDSROW + g * 8) * 2,
                       As + (size_t)(row0 + r) * K + k0 + g * 8);
        }
        #pragma unroll
        for (int t = 0; t < 2; t++) {
            int idx = tid + t * 256;
            int r = idx >> 2, g = idx & 3;
            cp_async16(sb + (uint32_t)(r * LDSROW + g * 8) * 2,
                       Bs + (size_t)(col0 + r) * K + k0 + g * 8);
        }
    };

    #pragma unroll
    for (int s = 0; s < STAGES - 1; s++) {
        load_chunk(s, s);
        cp_commit();
    }

    for (int c = 0; c < tot; c++) {
        if (c + STAGES - 1 < tot) load_chunk(c + STAGES - 1, (c + STAGES - 1) % STAGES);
        cp_commit();
        cp_wait<STAGES - 2>();
        __syncthreads();

        const int s = c % STAGES;
        const uint32_t abase = sm0 + s * TILE_B;
        const uint32_t bbase = sm0 + (STAGES + s) * TILE_B;

        #pragma unroll
        for (int ks = 0; ks < 2; ks++) {
            const int kc = ks * 16;
            uint32_t a_frag[4][4], b_frag[4][2];
            #pragma unroll
            for (int im = 0; im < 4; im++) {
                int row = warp_m * 64 + im * 16 + (lane & 15);
                int col = kc + ((lane >> 4) << 3);
                ldmatrix_x4(a_frag[im], abase + (uint32_t)(row * LDSROW + col) * 2);
            }
            #pragma unroll
            for (int ib = 0; ib < 2; ib++) {
                int n = warp_n * 32 + ib * 16 + (lane & 7) + ((lane >> 4) << 3);
                int col = kc + (lane & 8);
                uint32_t r4[4];
                ldmatrix_x4(r4, bbase + (uint32_t)(n * LDSROW + col) * 2);
                b_frag[ib * 2][0]     = r4[0]; b_frag[ib * 2][1]     = r4[1];
                b_frag[ib * 2 + 1][0] = r4[2]; b_frag[ib * 2 + 1][1] = r4[3];
            }
            #pragma unroll
            for (int im = 0; im < 4; im++)
                #pragma unroll
                for (int in = 0; in < 4; in++)
                    mma_16816(acc[im][in], a_frag[im], b_frag[in]);
        }
        __syncthreads();
    }

    #pragma unroll
    for (int im = 0; im < 4; im++) {
        const int row = row0 + warp_m * 64 + im * 16 + (lane >> 2);
        #pragma unroll
        for (int in = 0; in < 4; in++) {
            const int col = col0 + warp_n * 32 + in * 8 + 2 * (lane & 3);
            float2 v0 = make_float2(acc[im][in][0], acc[im][in][1]);
            float2 v1 = make_float2(acc[im][in][2], acc[im][in][3]);
            if (DO_CLIP) {
                v0.x = fminf(fmaxf(v0.x, -CLIPV), CLIPV);
                v0.y = fminf(fmaxf(v0.y, -CLIPV), CLIPV);
                v1.x = fminf(fmaxf(v1.x, -CLIPV), CLIPV);
                v1.y = fminf(fmaxf(v1.y, -CLIPV), CLIPV);
            }
            *(float2*)(Y + (size_t)row * N + col) = v0;
            *(float2*)(Y + (size_t)(row + 8) * N + col) = v1;
        }
    }
}

// ---------------------------------------------------------------------------
// Fused RMSNorm + RoPE, emitting split bf16 hi/lo.
// ---------------------------------------------------------------------------
__global__ void norm_rope_split(const float* __restrict__ src, const float* __restrict__ w,
                                __nv_bfloat16* __restrict__ dh,
                                __nv_bfloat16* __restrict__ dl, int nheads) {
    const int s = blockIdx.x, h = blockIdx.y, d = threadIdx.x;
    const size_t base = ((size_t)s * nheads + h) * HD;

    __shared__ float sh[HD];
    __shared__ float red[4];

    float x = src[base + d];
    float sq = x * x;
    #pragma unroll
    for (int o = 16; o; o >>= 1) sq += __shfl_xor_sync(0xffffffffu, sq, o);
    if ((d & 31) == 0) red[d >> 5] = sq;
    __syncthreads();

    float var = (red[0] + red[1] + red[2] + red[3]) * (1.0f / HD);
    float xn = x * rsqrtf(var + 1e-6f) * w[d];
    sh[d] = xn;
    __syncthreads();

    float inv_freq = powf(500000.0f, -(float)(d & 63) * (1.0f / 64.0f));
    float ang = (float)s * inv_freq;
    float sn, cs;
    sincosf(ang, &sn, &cs);
    float other = (d < 64) ? -sh[d + 64] : sh[d - 64];
    float val = xn * cs + other * sn;
    __nv_bfloat16 hb = __float2bfloat16(val);
    dh[base + d] = hb;
    dl[base + d] = __float2bfloat16(val - __bfloat162float(hb));
}

// ---------------------------------------------------------------------------
// Tensor-core flash attention, split-bf16, windowed + sink.
// grid=(32 qtiles reversed, 16 heads), 128 threads (4 warps x 16 q rows).
// ---------------------------------------------------------------------------
constexpr int AST = 136;                       // smem row stride (bf16 elems)
constexpr int TILE_E = 64 * AST;               // elems per 64x128 buffer
constexpr int ATTN_SMEM = 6 * TILE_E * 2;      // 104448 bytes

__global__ __launch_bounds__(128, 2) void attn_tc(
    const __nv_bfloat16* __restrict__ qh, const __nv_bfloat16* __restrict__ ql,
    const __nv_bfloat16* __restrict__ kh, const __nv_bfloat16* __restrict__ kl,
    const __nv_bfloat16* __restrict__ vh, const __nv_bfloat16* __restrict__ vl,
    const float* __restrict__ sinks,
    __nv_bfloat16* __restrict__ oh, __nv_bfloat16* __restrict__ ol) {
    extern __shared__ __nv_bfloat16 smb[];
    __nv_bfloat16* Qh = smb;
    __nv_bfloat16* Ql = smb + TILE_E;
    __nv_bfloat16* Kh = smb + 2 * TILE_E;
    __nv_bfloat16* Kl = smb + 3 * TILE_E;
    __nv_bfloat16* Vh = smb + 4 * TILE_E;
    __nv_bfloat16* Vl = smb + 5 * TILE_E;

    const int h = blockIdx.y;
    const int qt = (int)gridDim.x - 1 - (int)blockIdx.x;   // big tiles first
    const int q0 = qt << 6;
    const int kvh = h >> 2;
    const int tid = threadIdx.x;
    const int wid = tid >> 5;
    const int lane = tid & 31;

    // Q tile (hi/lo), one commit group
    {
        const __nv_bfloat16* sqh = qh + (size_t)q0 * DM + h * HD;
        const __nv_bfloat16* sql = ql + (size_t)q0 * DM + h * HD;
        for (int idx = tid; idx < 1024; idx += 128) {
            int r = idx >> 4, g = idx & 15;
            cp_async16(smem_u32(Qh + r * AST + g * 8), sqh + (size_t)r * DM + g * 8);
            cp_async16(smem_u32(Ql + r * AST + g * 8), sql + (size_t)r * DM + g * 8);
        }
        cp_commit();
    }

    float m[2] = {-1e30f, -1e30f}, lsum[2] = {0.0f, 0.0f};
    float acc_o[16][4];
    #pragma unroll
    for (int n = 0; n < 16; n++)
        #pragma unroll
        for (int t = 0; t < 4; t++) acc_o[n][t] = 0.0f;

    int lo = q0 - WIN + 1;
    if (lo < 0) lo = 0;
    const int kt_lo = lo >> 6;
    const int r0 = lane >> 2;

    for (int kt = kt_lo; kt <= qt; kt++) {
        const int k0 = kt << 6;
        __syncthreads();   // previous iteration done with K/V smem

        // issue K (group), then V (group)
        {
            const __nv_bfloat16* skh = kh + (size_t)k0 * KVD + kvh * HD;
            const __nv_bfloat16* skl = kl + (size_t)k0 * KVD + kvh * HD;
            for (int idx = tid; idx < 1024; idx += 128) {
                int r = idx >> 4, g = idx & 15;
                cp_async16(smem_u32(Kh + r * AST + g * 8), skh + (size_t)r * KVD + g * 8);
                cp_async16(smem_u32(Kl + r * AST + g * 8), skl + (size_t)r * KVD + g * 8);
            }
            cp_commit();
            const __nv_bfloat16* svh = vh + (size_t)k0 * KVD + kvh * HD;
            const __nv_bfloat16* svl = vl + (size_t)k0 * KVD + kvh * HD;
            for (int idx = tid; idx < 1024; idx += 128) {
                int r = idx >> 4, g = idx & 15;
                cp_async16(smem_u32(Vh + r * AST + g * 8), svh + (size_t)r * KVD + g * 8);
                cp_async16(smem_u32(Vl + r * AST + g * 8), svl + (size_t)r * KVD + g * 8);
            }
            cp_commit();
        }
        cp_wait<1>();          // K (and Q on first iter) ready
        __syncthreads();

        // ---- S = Q K^T (3 split passes fused) ----
        float acc_s[8][4];
        #pragma unroll
        for (int j = 0; j < 8; j++)
            #pragma unroll
            for (int t = 0; t < 4; t++) acc_s[j][t] = 0.0f;

        #pragma unroll
        for (int ks = 0; ks < 8; ks++) {
            uint32_t ah4[4], al4[4];
            const int qrow = wid * 16 + (lane & 15);
            const int qcol = ks * 16 + ((lane >> 4) << 3);
            ldmatrix_x4(ah4, smem_u32(Qh + qrow * AST + qcol));
            ldmatrix_x4(al4, smem_u32(Ql + qrow * AST + qcol));
            #pragma unroll
            for (int np = 0; np < 4; np++) {
                const int n = np * 16 + (lane & 7) + ((lane >> 4) << 3);
                const int col = ks * 16 + (lane & 8);
                uint32_t bh4[4], bl4[4];
                ldmatrix_x4(bh4, smem_u32(Kh + n * AST + col));
                ldmatrix_x4(bl4, smem_u32(Kl + n * AST + col));
                mma_16816(acc_s[2 * np],     ah4, bh4);
                mma_16816(acc_s[2 * np],     al4, bh4);
                mma_16816(acc_s[2 * np],     ah4, bl4);
                mma_16816(acc_s[2 * np + 1], ah4, bh4 + 2);
                mma_16816(acc_s[2 * np + 1], al4, bh4 + 2);
                mma_16816(acc_s[2 * np + 1], ah4, bl4 + 2);
            }
        }

        // ---- mask + online softmax on fragments ----
        #pragma unroll
        for (int half = 0; half < 2; half++) {
            const int qi = q0 + wid * 16 + r0 + half * 8;
            float rm = -1e30f;
            #pragma unroll
            for (int j = 0; j < 8; j++) {
                #pragma unroll
                for (int c = 0; c < 2; c++) {
                    const int ki = k0 + j * 8 + 2 * (lane & 3) + c;
                    float v = acc_s[j][half * 2 + c];
                    v = (ki <= qi && ki > qi - WIN) ? v * SCALE_F : -1e30f;
                    acc_s[j][half * 2 + c] = v;
                    rm = fmaxf(rm, v);
                }
            }
            rm = fmaxf(rm, __shfl_xor_sync(0xffffffffu, rm, 1));
            rm = fmaxf(rm, __shfl_xor_sync(0xffffffffu, rm, 2));
            const float nm = fmaxf(m[half], rm);
            const float sc = __expf(m[half] - nm);
            float rs = 0.0f;
            #pragma unroll
            for (int j = 0; j < 8; j++) {
                #pragma unroll
                for (int c = 0; c < 2; c++) {
                    float v = acc_s[j][half * 2 + c];
                    float p = (v > -1e29f) ? __expf(v - nm) : 0.0f;
                    acc_s[j][half * 2 + c] = p;
                    rs += p;
                }
            }
            rs += __shfl_xor_sync(0xffffffffu, rs, 1);
            rs += __shfl_xor_sync(0xffffffffu, rs, 2);
            lsum[half] = lsum[half] * sc + rs;
            m[half] = nm;
            #pragma unroll
            for (int n = 0; n < 16; n++) {
                acc_o[n][half * 2]     *= sc;
                acc_o[n][half * 2 + 1] *= sc;
            }
        }

        // ---- repack P into A fragments (hi + lo) ----
        uint32_t aPh[4][4], aPl[4][4];
        #pragma unroll
        for (int kk = 0; kk < 4; kk++) {
            #pragma unroll
            for (int t = 0; t < 4; t++) {
                const int j = 2 * kk + (t >> 1);
                const int c0 = (t & 1) * 2;
                const float p0 = acc_s[j][c0], p1 = acc_s[j][c0 + 1];
                __nv_bfloat162 hp = __floats2bfloat162_rn(p0, p1);
                __nv_bfloat162 lp = __floats2bfloat162_rn(p0 - __low2float(hp),
                                                          p1 - __high2float(hp));
                aPh[kk][t] = *(uint32_t*)&hp;
                aPl[kk][t] = *(uint32_t*)&lp;
            }
        }

        cp_wait<0>();          // V ready
        __syncthreads();

        // ---- O += P V (3 split passes fused) ----
        #pragma unroll
        for (int kk = 0; kk < 4; kk++) {
            const int vrow = kk * 16 + (lane & 15);
            const int vcol = (lane >> 4) << 3;
            #pragma unroll
            for (int np = 0; np < 8; np++) {
                uint32_t bh4[4], bl4[4];
                ldmatrix_x4_trans(bh4, smem_u32(Vh + vrow * AST + np * 16 + vcol));
                mma_16816(acc_o[2 * np],     aPh[kk], bh4);
                mma_16816(acc_o[2 * np + 1], aPh[kk], bh4 + 2);
                mma_16816(acc_o[2 * np],     aPl[kk], bh4);
                mma_16816(acc_o[2 * np + 1], aPl[kk], bh4 + 2);
                ldmatrix_x4_trans(bl4, smem_u32(Vl + vrow * AST + np * 16 + vcol));
                mma_16816(acc_o[2 * np],     aPh[kk], bl4);
                mma_16816(acc_o[2 * np + 1], aPh[kk], bl4 + 2);
            }
        }
    }

    // ---- sink fold + write split-bf16 output ----
    const float snk = sinks[h];
    #pragma unroll
    for (int half = 0; half < 2; half++) {
        const float M = fmaxf(m[half], snk);
        const float denom = lsum[half] * __expf(m[half] - M) + __expf(snk - M);
        const float ns = __expf(m[half] - M) / denom;
        const int row = q0 + wid * 16 + r0 + half * 8;
        #pragma unroll
        for (int n = 0; n < 16; n++) {
            const float v0 = acc_o[n][half * 2] * ns;
            const float v1 = acc_o[n][half * 2 + 1] * ns;
            __nv_bfloat162 hp = __floats2bfloat162_rn(v0, v1);
            __nv_bfloat162 lp = __floats2bfloat162_rn(v0 - __low2float(hp),
                                                      v1 - __high2float(hp));
            const size_t off = (size_t)row * DM + h * HD + n * 8 + 2 * (lane & 3);
            *(__nv_bfloat162*)(oh + off) = hp;
            *(__nv_bfloat162*)(ol + off) = lp;
        }
    }
}

// ---------------------------------------------------------------------------
// Launch
// ---------------------------------------------------------------------------
extern "C" void kernel_launch(void* const* d_in, const int* in_sizes, int n_in,
                              void* d_out, int out_size) {
    const float* x     = (const float*)d_in[0];
    const float* w_q   = (const float*)d_in[1];
    const float* w_k   = (const float*)d_in[2];
    const float* w_v   = (const float*)d_in[3];
    const float* w_out = (const float*)d_in[4];
    const float* qnw   = (const float*)d_in[5];
    const float* knw   = (const float*)d_in[6];
    const float* sinks = (const float*)d_in[7];
    float* out = (float*)d_out;

    float *pq, *pk, *pv;
    cudaGetSymbolAddress((void**)&pq, g_q);
    cudaGetSymbolAddress((void**)&pk, g_k);
    cudaGetSymbolAddress((void**)&pv, g_v);

    __nv_bfloat16 *xh, *xl, *wqh, *wql, *wkh, *wkl, *wvh, *wvl, *woh, *wol, *ah, *al;
    __nv_bfloat16 *qnh, *qnl, *knh, *knl, *vnh, *vnl;
    cudaGetSymbolAddress((void**)&xh,  g_xh);  cudaGetSymbolAddress((void**)&xl,  g_xl);
    cudaGetSymbolAddress((void**)&wqh, g_wqh); cudaGetSymbolAddress((void**)&wql, g_wql);
    cudaGetSymbolAddress((void**)&wkh, g_wkh); cudaGetSymbolAddress((void**)&wkl, g_wkl);
    cudaGetSymbolAddress((void**)&wvh, g_wvh); cudaGetSymbolAddress((void**)&wvl, g_wvl);
    cudaGetSymbolAddress((void**)&woh, g_woh); cudaGetSymbolAddress((void**)&wol, g_wol);
    cudaGetSymbolAddress((void**)&ah,  g_ah);  cudaGetSymbolAddress((void**)&al,  g_al);
    cudaGetSymbolAddress((void**)&qnh, g_qnh); cudaGetSymbolAddress((void**)&qnl, g_qnl);
    cudaGetSymbolAddress((void**)&knh, g_knh); cudaGetSymbolAddress((void**)&knl, g_knl);
    cudaGetSymbolAddress((void**)&vnh, g_vnh); cudaGetSymbolAddress((void**)&vnl, g_vnl);

    auto split = [&](const float* src, __nv_bfloat16* h, __nv_bfloat16* l, int n) {
        int n4 = n >> 2;
        split_kernel<<<(n4 + 255) / 256, 256>>>(src, h, l, n4);
    };
    split(x,     xh,  xl,  SEQ * DM);
    split(w_q,   wqh, wql, DM * DM);
    split(w_k,   wkh, wkl, KVD * DM);
    split(w_v,   wvh, wvl, KVD * DM);
    split(w_out, woh, wol, DM * DM);

    cudaFuncSetAttribute(tc_gemm<true>,  cudaFuncAttributeMaxDynamicSharedMemorySize, GEMM_SMEM);
    cudaFuncSetAttribute(tc_gemm<false>, cudaFuncAttributeMaxDynamicSharedMemorySize, GEMM_SMEM);

    // Projections (HMMA, split x3, clip in epilogue)
    tc_gemm<true><<<dim3(DM / 128, SEQ / 128), 256, GEMM_SMEM>>>(xh, xl, wqh, wql, pq, DM, DM);
    tc_gemm<true><<<dim3(KVD / 128, SEQ / 128), 256, GEMM_SMEM>>>(xh, xl, wkh, wkl, pk, DM, KVD);
    tc_gemm<true><<<dim3(KVD / 128, SEQ / 128), 256, GEMM_SMEM>>>(xh, xl, wvh, wvl, pv, DM, KVD);

    // RMSNorm + RoPE -> split bf16; V -> split bf16
    norm_rope_split<<<dim3(SEQ, NH), 128>>>(pq, qnw, qnh, qnl, NH);
    norm_rope_split<<<dim3(SEQ, NKV), 128>>>(pk, knw, knh, knl, NKV);
    split(pv, vnh, vnl, SEQ * KVD);

    // Tensor-core windowed flash attention + sink; emits split bf16 output
    cudaFuncSetAttribute(attn_tc, cudaFuncAttributeMaxDynamicSharedMemorySize, ATTN_SMEM);
    attn_tc<<<dim3(SEQ / 64, NH), 128, ATTN_SMEM>>>(qnh, qnl, knh, knl, vnh, vnl,
                                                    sinks, ah, al);

    // Output projection (HMMA, split x3)
    tc_gemm<false><<<dim3(DM / 128, SEQ / 128), 256, GEMM_SMEM>>>(ah, al, woh, wol, out, DM, DM);
}

// round 9
// speedup vs baseline: 3.9333x; 1.8713x over previous
#include <cuda_runtime.h>
#include <cuda_bf16.h>
#include <math.h>
#include <stdint.h>

// Problem constants
constexpr int SEQ  = 2048;
constexpr int DM   = 2048;
constexpr int NH   = 16;
constexpr int NKV  = 4;
constexpr int HD   = 128;
constexpr int WIN  = 1024;
constexpr int KVD  = NKV * HD;   // 512
constexpr float CLIPV = 8.0f;
constexpr float SCALE_F = 0.08838834764831845f; // 1/sqrt(128)

// ---------------------------------------------------------------------------
// Static scratch (no allocations allowed)
// ---------------------------------------------------------------------------
__device__ float g_q[SEQ * DM];
__device__ float g_k[SEQ * KVD];
__device__ float g_v[SEQ * KVD];

__device__ __nv_bfloat16 g_xh[SEQ * DM],  g_xl[SEQ * DM];
__device__ __nv_bfloat16 g_wqh[DM * DM],  g_wql[DM * DM];
__device__ __nv_bfloat16 g_wkh[KVD * DM], g_wkl[KVD * DM];
__device__ __nv_bfloat16 g_wvh[KVD * DM], g_wvl[KVD * DM];
__device__ __nv_bfloat16 g_woh[DM * DM],  g_wol[DM * DM];
__device__ __nv_bfloat16 g_ah[SEQ * DM],  g_al[SEQ * DM];      // attn out hi/lo
__device__ __nv_bfloat16 g_qnh[SEQ * DM], g_qnl[SEQ * DM];     // q normed/roped hi/lo
__device__ __nv_bfloat16 g_knh[SEQ * KVD], g_knl[SEQ * KVD];   // k normed/roped hi/lo
__device__ __nv_bfloat16 g_vnh[SEQ * KVD], g_vnl[SEQ * KVD];   // v hi/lo

// ---------------------------------------------------------------------------
// PTX helpers (sm_80+ instruction set — ptxas here targets plain sm_103)
// ---------------------------------------------------------------------------
__device__ __forceinline__ uint32_t smem_u32(const void* p) {
    uint32_t a;
    asm("{ .reg .u64 t; cvta.to.shared.u64 t, %1; cvt.u32.u64 %0, t; }"
        : "=r"(a) : "l"(p));
    return a;
}

__device__ __forceinline__ void cp_async16(uint32_t sp, const void* gp) {
    asm volatile("cp.async.cg.shared.global [%0], [%1], 16;"
                 :: "r"(sp), "l"(gp) : "memory");
}
__device__ __forceinline__ void cp_commit() {
    asm volatile("cp.async.commit_group;" ::: "memory");
}
template <int N>
__device__ __forceinline__ void cp_wait() {
    asm volatile("cp.async.wait_group %0;" :: "n"(N) : "memory");
}

__device__ __forceinline__ void ldmatrix_x4(uint32_t* r, uint32_t addr) {
    asm volatile("ldmatrix.sync.aligned.m8n8.x4.shared.b16 {%0,%1,%2,%3}, [%4];"
                 : "=r"(r[0]), "=r"(r[1]), "=r"(r[2]), "=r"(r[3]) : "r"(addr));
}
__device__ __forceinline__ void ldmatrix_x4_trans(uint32_t* r, uint32_t addr) {
    asm volatile("ldmatrix.sync.aligned.m8n8.x4.trans.shared.b16 {%0,%1,%2,%3}, [%4];"
                 : "=r"(r[0]), "=r"(r[1]), "=r"(r[2]), "=r"(r[3]) : "r"(addr));
}

__device__ __forceinline__ void mma_16816(float* c, const uint32_t* a, const uint32_t* b) {
    asm volatile(
        "mma.sync.aligned.m16n8k16.row.col.f32.bf16.bf16.f32 "
        "{%0,%1,%2,%3}, {%4,%5,%6,%7}, {%8,%9}, {%0,%1,%2,%3};"
        : "+f"(c[0]), "+f"(c[1]), "+f"(c[2]), "+f"(c[3])
        : "r"(a[0]), "r"(a[1]), "r"(a[2]), "r"(a[3]), "r"(b[0]), "r"(b[1]));
}

// ---------------------------------------------------------------------------
// Split fp32 -> (hi, lo) bf16
// ---------------------------------------------------------------------------
__global__ void split_kernel(const float* __restrict__ x,
                             __nv_bfloat16* __restrict__ hi,
                             __nv_bfloat16* __restrict__ lo, int n4) {
    int i = blockIdx.x * 256 + threadIdx.x;
    if (i >= n4) return;
    float4 v = ((const float4*)x)[i];
    __nv_bfloat16 h0 = __float2bfloat16(v.x);
    __nv_bfloat16 h1 = __float2bfloat16(v.y);
    __nv_bfloat16 h2 = __float2bfloat16(v.z);
    __nv_bfloat16 h3 = __float2bfloat16(v.w);
    __nv_bfloat16 l0 = __float2bfloat16(v.x - __bfloat162float(h0));
    __nv_bfloat16 l1 = __float2bfloat16(v.y - __bfloat162float(h1));
    __nv_bfloat16 l2 = __float2bfloat16(v.z - __bfloat162float(h2));
    __nv_bfloat16 l3 = __float2bfloat16(v.w - __bfloat162float(h3));
    __nv_bfloat162 hp0 = __halves2bfloat162(h0, h1);
    __nv_bfloat162 hp1 = __halves2bfloat162(h2, h3);
    __nv_bfloat162 lp0 = __halves2bfloat162(l0, l1);
    __nv_bfloat162 lp1 = __halves2bfloat162(l2, l3);
    uint2 hv, lv;
    hv.x = *(uint32_t*)&hp0; hv.y = *(uint32_t*)&hp1;
    lv.x = *(uint32_t*)&lp0; lv.y = *(uint32_t*)&lp1;
    ((uint2*)hi)[i] = hv;
    ((uint2*)lo)[i] = lv;
}

// ---------------------------------------------------------------------------
// GEMM v2 body: Y = A @ B^T in ONE K-sweep, 3 split MMAs per chunk.
// Block 128x128, BK=32, 2-stage cp.async pipeline, 256 threads.
// Per stage smem: Ah | Al | Bh | Bl, each 128x32 bf16 (LDSROW=40 padded).
// ---------------------------------------------------------------------------
constexpr int LDSROW = 40;
constexpr int TILE_B = 128 * LDSROW * 2;    // 10240 B per tile
constexpr int CHUNK_B = 4 * TILE_B;         // 40960 B per stage
constexpr int GEMM_SMEM = 2 * CHUNK_B;      // 81920 B

template <bool DO_CLIP>
__device__ __forceinline__ void gemm_body(
    const __nv_bfloat16* __restrict__ Ah, const __nv_bfloat16* __restrict__ Al,
    const __nv_bfloat16* __restrict__ Bh, const __nv_bfloat16* __restrict__ Bl,
    float* __restrict__ Y, int K, int N, int row0, int col0, char* dsm) {
    const uint32_t sm0 = smem_u32(dsm);
    const int tid = threadIdx.x;
    const int wid = tid >> 5;
    const int lane = tid & 31;
    const int warp_m = wid & 1;
    const int warp_n = wid >> 1;
    const int NC = K >> 5;

    float acc[4][4][4];
    #pragma unroll
    for (int i = 0; i < 4; i++)
        #pragma unroll
        for (int j = 0; j < 4; j++)
            #pragma unroll
            for (int t = 0; t < 4; t++) acc[i][j][t] = 0.0f;

    auto load_chunk = [&](int c, int s) {
        const int k0 = c << 5;
        const uint32_t b = sm0 + s * CHUNK_B;
        #pragma unroll
        for (int t = 0; t < 2; t++) {
            int idx = tid + t * 256;
            int r = idx >> 2, g = idx & 3;
            uint32_t off = (uint32_t)(r * LDSROW + g * 8) * 2;
            const size_t ga = (size_t)(row0 + r) * K + k0 + g * 8;
            cp_async16(b + off, Ah + ga);
            cp_async16(b + TILE_B + off, Al + ga);
            const size_t gb = (size_t)(col0 + r) * K + k0 + g * 8;
            cp_async16(b + 2 * TILE_B + off, Bh + gb);
            cp_async16(b + 3 * TILE_B + off, Bl + gb);
        }
    };

    load_chunk(0, 0);
    cp_commit();

    for (int c = 0; c < NC; c++) {
        if (c + 1 < NC) {
            load_chunk(c + 1, (c + 1) & 1);
            cp_commit();
            cp_wait<1>();
        } else {
            cp_wait<0>();
        }
        __syncthreads();

        const uint32_t b = sm0 + (c & 1) * CHUNK_B;
        #pragma unroll
        for (int ks = 0; ks < 2; ks++) {
            const int kc = ks * 16;
            uint32_t ah4[4][4], al4[4][4], bh[4][2], bl[4][2];
            #pragma unroll
            for (int im = 0; im < 4; im++) {
                int row = warp_m * 64 + im * 16 + (lane & 15);
                int col = kc + ((lane >> 4) << 3);
                ldmatrix_x4(ah4[im], b + (uint32_t)(row * LDSROW + col) * 2);
            }
            #pragma unroll
            for (int ib = 0; ib < 2; ib++) {
                int n = warp_n * 32 + ib * 16 + (lane & 7) + ((lane >> 4) << 3);
                int col = kc + (lane & 8);
                uint32_t r4[4];
                ldmatrix_x4(r4, b + 2 * TILE_B + (uint32_t)(n * LDSROW + col) * 2);
                bh[ib * 2][0] = r4[0]; bh[ib * 2][1] = r4[1];
                bh[ib * 2 + 1][0] = r4[2]; bh[ib * 2 + 1][1] = r4[3];
                ldmatrix_x4(r4, b + 3 * TILE_B + (uint32_t)(n * LDSROW + col) * 2);
                bl[ib * 2][0] = r4[0]; bl[ib * 2][1] = r4[1];
                bl[ib * 2 + 1][0] = r4[2]; bl[ib * 2 + 1][1] = r4[3];
            }
            // sweep 1: Ah*Bh
            #pragma unroll
            for (int im = 0; im < 4; im++)
                #pragma unroll
                for (int in = 0; in < 4; in++)
                    mma_16816(acc[im][in], ah4[im], bh[in]);
            // sweep 2: Ah*Bl (bl dies after this)
            #pragma unroll
            for (int im = 0; im < 4; im++)
                #pragma unroll
                for (int in = 0; in < 4; in++)
                    mma_16816(acc[im][in], ah4[im], bl[in]);
            // load Al, sweep 3: Al*Bh
            #pragma unroll
            for (int im = 0; im < 4; im++) {
                int row = warp_m * 64 + im * 16 + (lane & 15);
                int col = kc + ((lane >> 4) << 3);
                ldmatrix_x4(al4[im], b + TILE_B + (uint32_t)(row * LDSROW + col) * 2);
            }
            #pragma unroll
            for (int im = 0; im < 4; im++)
                #pragma unroll
                for (int in = 0; in < 4; in++)
                    mma_16816(acc[im][in], al4[im], bh[in]);
        }
        __syncthreads();
    }

    #pragma unroll
    for (int im = 0; im < 4; im++) {
        const int row = row0 + warp_m * 64 + im * 16 + (lane >> 2);
        #pragma unroll
        for (int in = 0; in < 4; in++) {
            const int col = col0 + warp_n * 32 + in * 8 + 2 * (lane & 3);
            float2 v0 = make_float2(acc[im][in][0], acc[im][in][1]);
            float2 v1 = make_float2(acc[im][in][2], acc[im][in][3]);
            if (DO_CLIP) {
                v0.x = fminf(fmaxf(v0.x, -CLIPV), CLIPV);
                v0.y = fminf(fmaxf(v0.y, -CLIPV), CLIPV);
                v1.x = fminf(fmaxf(v1.x, -CLIPV), CLIPV);
                v1.y = fminf(fmaxf(v1.y, -CLIPV), CLIPV);
            }
            *(float2*)(Y + (size_t)row * N + col) = v0;
            *(float2*)(Y + (size_t)(row + 8) * N + col) = v1;
        }
    }
}

// Fused Q/K/V projection: grid (24, 16); x 0-15 -> Q, 16-19 -> K, 20-23 -> V.
__global__ __launch_bounds__(256, 2) void qkv_gemm() {
    extern __shared__ char dsm[];
    const int cx = blockIdx.x;
    const int row0 = blockIdx.y << 7;
    if (cx < 16)
        gemm_body<true>(g_xh, g_xl, g_wqh, g_wql, g_q, DM, DM, row0, cx << 7, dsm);
    else if (cx < 20)
        gemm_body<true>(g_xh, g_xl, g_wkh, g_wkl, g_k, DM, KVD, row0, (cx - 16) << 7, dsm);
    else
        gemm_body<true>(g_xh, g_xl, g_wvh, g_wvl, g_v, DM, KVD, row0, (cx - 20) << 7, dsm);
}

__global__ __launch_bounds__(256, 2) void out_gemm(float* __restrict__ out) {
    extern __shared__ char dsm[];
    gemm_body<false>(g_ah, g_al, g_woh, g_wol, out, DM, DM,
                     blockIdx.y << 7, blockIdx.x << 7, dsm);
}

// ---------------------------------------------------------------------------
// Fused RMSNorm + RoPE, emitting split bf16 hi/lo.
// ---------------------------------------------------------------------------
__global__ void norm_rope_split(const float* __restrict__ src, const float* __restrict__ w,
                                __nv_bfloat16* __restrict__ dh,
                                __nv_bfloat16* __restrict__ dl, int nheads) {
    const int s = blockIdx.x, h = blockIdx.y, d = threadIdx.x;
    const size_t base = ((size_t)s * nheads + h) * HD;

    __shared__ float sh[HD];
    __shared__ float red[4];

    float x = src[base + d];
    float sq = x * x;
    #pragma unroll
    for (int o = 16; o; o >>= 1) sq += __shfl_xor_sync(0xffffffffu, sq, o);
    if ((d & 31) == 0) red[d >> 5] = sq;
    __syncthreads();

    float var = (red[0] + red[1] + red[2] + red[3]) * (1.0f / HD);
    float xn = x * rsqrtf(var + 1e-6f) * w[d];
    sh[d] = xn;
    __syncthreads();

    float inv_freq = powf(500000.0f, -(float)(d & 63) * (1.0f / 64.0f));
    float ang = (float)s * inv_freq;
    float sn, cs;
    sincosf(ang, &sn, &cs);
    float other = (d < 64) ? -sh[d + 64] : sh[d - 64];
    float val = xn * cs + other * sn;
    __nv_bfloat16 hb = __float2bfloat16(val);
    dh[base + d] = hb;
    dl[base + d] = __float2bfloat16(val - __bfloat162float(hb));
}

// ---------------------------------------------------------------------------
// Tensor-core flash attention v2: two GQA heads per CTA (shared K/V),
// double-buffered K/V prefetch. grid = (8 head-pairs, 32 qtiles rev),
// 256 threads: warps 0-3 -> head 2g, warps 4-7 -> head 2g+1.
// ---------------------------------------------------------------------------
constexpr int AST = 136;                     // smem row stride (bf16)
constexpr int TILE_E = 64 * AST;             // 8704 elems per 64x128 tile
constexpr int ATTN_SMEM = 12 * TILE_E * 2;   // 208896 B

__global__ __launch_bounds__(256, 1) void attn_tc(const float* __restrict__ sinks) {
    extern __shared__ __nv_bfloat16 smb[];
    // layout: [QhA QlA QhB QlB | Kh0 Kl0 Kh1 Kl1 | Vh0 Vl0 Vh1 Vl1]
    const int g = blockIdx.x;                  // head pair
    const int qt = 31 - (int)blockIdx.y;       // big q-tiles first
    const int q0 = qt << 6;
    const int kvh = g >> 1;
    const int tid = threadIdx.x;
    const int wid = tid >> 5;
    const int lane = tid & 31;
    const int hsel = wid >> 2;                 // 0 or 1
    const int wq = wid & 3;                    // warp within head
    const int h = g * 2 + hsel;

    __nv_bfloat16* Qh = smb + hsel * 2 * TILE_E;
    __nv_bfloat16* Ql = Qh + TILE_E;

    // Q tiles for both heads (group 0)
    for (int idx = tid; idx < 2048; idx += 256) {
        int hd = idx >> 10;
        int rem = idx & 1023;
        int r = rem >> 4, c = rem & 15;
        const size_t go = (size_t)(q0 + r) * DM + (g * 2 + hd) * HD + c * 8;
        cp_async16(smem_u32(smb + hd * 2 * TILE_E + r * AST + c * 8), g_qnh + go);
        cp_async16(smem_u32(smb + (hd * 2 + 1) * TILE_E + r * AST + c * 8), g_qnl + go);
    }
    cp_commit();

    auto load_kv = [&](int kt, int b) {
        const int k0 = kt << 6;
        __nv_bfloat16* Khp = smb + (4 + 2 * b) * TILE_E;
        __nv_bfloat16* Klp = Khp + TILE_E;
        __nv_bfloat16* Vhp = smb + (8 + 2 * b) * TILE_E;
        __nv_bfloat16* Vlp = Vhp + TILE_E;
        for (int idx = tid; idx < 1024; idx += 256) {
            int r = idx >> 4, c = idx & 15;
            const size_t go = (size_t)(k0 + r) * KVD + kvh * HD + c * 8;
            cp_async16(smem_u32(Khp + r * AST + c * 8), g_knh + go);
            cp_async16(smem_u32(Klp + r * AST + c * 8), g_knl + go);
            cp_async16(smem_u32(Vhp + r * AST + c * 8), g_vnh + go);
            cp_async16(smem_u32(Vlp + r * AST + c * 8), g_vnl + go);
        }
    };

    int lo = q0 - WIN + 1;
    if (lo < 0) lo = 0;
    const int kt_lo = lo >> 6;
    load_kv(kt_lo, 0);
    cp_commit();

    float m[2] = {-1e30f, -1e30f}, lsum[2] = {0.0f, 0.0f};
    float acc_o[16][4];
    #pragma unroll
    for (int n = 0; n < 16; n++)
        #pragma unroll
        for (int t = 0; t < 4; t++) acc_o[n][t] = 0.0f;

    const int r0 = lane >> 2;

    for (int kt = kt_lo; kt <= qt; kt++) {
        const int b = (kt - kt_lo) & 1;
        const int k0 = kt << 6;
        if (kt < qt) {
            load_kv(kt + 1, b ^ 1);
            cp_commit();
            cp_wait<1>();
        } else {
            cp_wait<0>();
        }
        __syncthreads();

        __nv_bfloat16* Kh = smb + (4 + 2 * b) * TILE_E;
        __nv_bfloat16* Kl = Kh + TILE_E;
        __nv_bfloat16* Vh = smb + (8 + 2 * b) * TILE_E;
        __nv_bfloat16* Vl = Vh + TILE_E;

        // ---- S = Q K^T (3 split passes) ----
        float acc_s[8][4];
        #pragma unroll
        for (int j = 0; j < 8; j++)
            #pragma unroll
            for (int t = 0; t < 4; t++) acc_s[j][t] = 0.0f;

        #pragma unroll
        for (int ks = 0; ks < 8; ks++) {
            uint32_t ah4[4], al4[4];
            const int qrow = wq * 16 + (lane & 15);
            const int qcol = ks * 16 + ((lane >> 4) << 3);
            ldmatrix_x4(ah4, smem_u32(Qh + qrow * AST + qcol));
            ldmatrix_x4(al4, smem_u32(Ql + qrow * AST + qcol));
            #pragma unroll
            for (int np = 0; np < 4; np++) {
                const int n = np * 16 + (lane & 7) + ((lane >> 4) << 3);
                const int col = ks * 16 + (lane & 8);
                uint32_t bh4[4], bl4[4];
                ldmatrix_x4(bh4, smem_u32(Kh + n * AST + col));
                ldmatrix_x4(bl4, smem_u32(Kl + n * AST + col));
                mma_16816(acc_s[2 * np],     ah4, bh4);
                mma_16816(acc_s[2 * np],     al4, bh4);
                mma_16816(acc_s[2 * np],     ah4, bl4);
                mma_16816(acc_s[2 * np + 1], ah4, bh4 + 2);
                mma_16816(acc_s[2 * np + 1], al4, bh4 + 2);
                mma_16816(acc_s[2 * np + 1], ah4, bl4 + 2);
            }
        }

        // ---- mask + online softmax ----
        #pragma unroll
        for (int half = 0; half < 2; half++) {
            const int qi = q0 + wq * 16 + r0 + half * 8;
            float rm = -1e30f;
            #pragma unroll
            for (int j = 0; j < 8; j++) {
                #pragma unroll
                for (int c = 0; c < 2; c++) {
                    const int ki = k0 + j * 8 + 2 * (lane & 3) + c;
                    float v = acc_s[j][half * 2 + c];
                    v = (ki <= qi && ki > qi - WIN) ? v * SCALE_F : -1e30f;
                    acc_s[j][half * 2 + c] = v;
                    rm = fmaxf(rm, v);
                }
            }
            rm = fmaxf(rm, __shfl_xor_sync(0xffffffffu, rm, 1));
            rm = fmaxf(rm, __shfl_xor_sync(0xffffffffu, rm, 2));
            const float nm = fmaxf(m[half], rm);
            const float sc = __expf(m[half] - nm);
            float rs = 0.0f;
            #pragma unroll
            for (int j = 0; j < 8; j++) {
                #pragma unroll
                for (int c = 0; c < 2; c++) {
                    float v = acc_s[j][half * 2 + c];
                    float p = (v > -1e29f) ? __expf(v - nm) : 0.0f;
                    acc_s[j][half * 2 + c] = p;
                    rs += p;
                }
            }
            rs += __shfl_xor_sync(0xffffffffu, rs, 1);
            rs += __shfl_xor_sync(0xffffffffu, rs, 2);
            lsum[half] = lsum[half] * sc + rs;
            m[half] = nm;
            #pragma unroll
            for (int n = 0; n < 16; n++) {
                acc_o[n][half * 2]     *= sc;
                acc_o[n][half * 2 + 1] *= sc;
            }
        }

        // ---- repack P into A fragments (hi + lo) ----
        uint32_t aPh[4][4], aPl[4][4];
        #pragma unroll
        for (int kk = 0; kk < 4; kk++) {
            #pragma unroll
            for (int t = 0; t < 4; t++) {
                const int j = 2 * kk + (t >> 1);
                const int c0 = (t & 1) * 2;
                const float p0 = acc_s[j][c0], p1 = acc_s[j][c0 + 1];
                __nv_bfloat162 hp = __floats2bfloat162_rn(p0, p1);
                __nv_bfloat162 lp = __floats2bfloat162_rn(p0 - __low2float(hp),
                                                          p1 - __high2float(hp));
                aPh[kk][t] = *(uint32_t*)&hp;
                aPl[kk][t] = *(uint32_t*)&lp;
            }
        }

        // ---- O += P V (3 split passes) ----
        #pragma unroll
        for (int kk = 0; kk < 4; kk++) {
            const int vrow = kk * 16 + (lane & 15);
            const int vcol = (lane >> 4) << 3;
            #pragma unroll
            for (int np = 0; np < 8; np++) {
                uint32_t bh4[4], bl4[4];
                ldmatrix_x4_trans(bh4, smem_u32(Vh + vrow * AST + np * 16 + vcol));
                mma_16816(acc_o[2 * np],     aPh[kk], bh4);
                mma_16816(acc_o[2 * np + 1], aPh[kk], bh4 + 2);
                mma_16816(acc_o[2 * np],     aPl[kk], bh4);
                mma_16816(acc_o[2 * np + 1], aPl[kk], bh4 + 2);
                ldmatrix_x4_trans(bl4, smem_u32(Vl + vrow * AST + np * 16 + vcol));
                mma_16816(acc_o[2 * np],     aPh[kk], bl4);
                mma_16816(acc_o[2 * np + 1], aPh[kk], bl4 + 2);
            }
        }
        __syncthreads();
    }

    // ---- sink fold + write split-bf16 output ----
    const float snk = sinks[h];
    #pragma unroll
    for (int half = 0; half < 2; half++) {
        const float M = fmaxf(m[half], snk);
        const float denom = lsum[half] * __expf(m[half] - M) + __expf(snk - M);
        const float ns = __expf(m[half] - M) / denom;
        const int row = q0 + wq * 16 + r0 + half * 8;
        #pragma unroll
        for (int n = 0; n < 16; n++) {
            const float v0 = acc_o[n][half * 2] * ns;
            const float v1 = acc_o[n][half * 2 + 1] * ns;
            __nv_bfloat162 hp = __floats2bfloat162_rn(v0, v1);
            __nv_bfloat162 lp = __floats2bfloat162_rn(v0 - __low2float(hp),
                                                      v1 - __high2float(hp));
            const size_t off = (size_t)row * DM + h * HD + n * 8 + 2 * (lane & 3);
            *(__nv_bfloat162*)(g_ah + off) = hp;
            *(__nv_bfloat162*)(g_al + off) = lp;
        }
    }
}

// ---------------------------------------------------------------------------
// Launch
// ---------------------------------------------------------------------------
extern "C" void kernel_launch(void* const* d_in, const int* in_sizes, int n_in,
                              void* d_out, int out_size) {
    const float* x     = (const float*)d_in[0];
    const float* w_q   = (const float*)d_in[1];
    const float* w_k   = (const float*)d_in[2];
    const float* w_v   = (const float*)d_in[3];
    const float* w_out = (const float*)d_in[4];
    const float* qnw   = (const float*)d_in[5];
    const float* knw   = (const float*)d_in[6];
    const float* sinks = (const float*)d_in[7];
    float* out = (float*)d_out;

    float *pq, *pk, *pv;
    cudaGetSymbolAddress((void**)&pq, g_q);
    cudaGetSymbolAddress((void**)&pk, g_k);
    cudaGetSymbolAddress((void**)&pv, g_v);

    __nv_bfloat16 *xh, *xl, *wqh, *wql, *wkh, *wkl, *wvh, *wvl, *woh, *wol;
    __nv_bfloat16 *qnh, *qnl, *knh, *knl, *vnh, *vnl;
    cudaGetSymbolAddress((void**)&xh,  g_xh);  cudaGetSymbolAddress((void**)&xl,  g_xl);
    cudaGetSymbolAddress((void**)&wqh, g_wqh); cudaGetSymbolAddress((void**)&wql, g_wql);
    cudaGetSymbolAddress((void**)&wkh, g_wkh); cudaGetSymbolAddress((void**)&wkl, g_wkl);
    cudaGetSymbolAddress((void**)&wvh, g_wvh); cudaGetSymbolAddress((void**)&wvl, g_wvl);
    cudaGetSymbolAddress((void**)&woh, g_woh); cudaGetSymbolAddress((void**)&wol, g_wol);
    cudaGetSymbolAddress((void**)&qnh, g_qnh); cudaGetSymbolAddress((void**)&qnl, g_qnl);
    cudaGetSymbolAddress((void**)&knh, g_knh); cudaGetSymbolAddress((void**)&knl, g_knl);
    cudaGetSymbolAddress((void**)&vnh, g_vnh); cudaGetSymbolAddress((void**)&vnl, g_vnl);

    auto split = [&](const float* src, __nv_bfloat16* h, __nv_bfloat16* l, int n) {
        int n4 = n >> 2;
        split_kernel<<<(n4 + 255) / 256, 256>>>(src, h, l, n4);
    };
    split(x,     xh,  xl,  SEQ * DM);
    split(w_q,   wqh, wql, DM * DM);
    split(w_k,   wkh, wkl, KVD * DM);
    split(w_v,   wvh, wvl, KVD * DM);
    split(w_out, woh, wol, DM * DM);

    cudaFuncSetAttribute(qkv_gemm, cudaFuncAttributeMaxDynamicSharedMemorySize, GEMM_SMEM);
    cudaFuncSetAttribute(out_gemm, cudaFuncAttributeMaxDynamicSharedMemorySize, GEMM_SMEM);
    cudaFuncSetAttribute(attn_tc,  cudaFuncAttributeMaxDynamicSharedMemorySize, ATTN_SMEM);

    // Fused Q/K/V projections (one launch, 384 CTAs)
    qkv_gemm<<<dim3(24, 16), 256, GEMM_SMEM>>>();

    // RMSNorm + RoPE -> split bf16; V -> split bf16
    norm_rope_split<<<dim3(SEQ, NH), 128>>>(pq, qnw, qnh, qnl, NH);
    norm_rope_split<<<dim3(SEQ, NKV), 128>>>(pk, knw, knh, knl, NKV);
    split(pv, vnh, vnl, SEQ * KVD);

    // Windowed flash attention + sink (2 heads/CTA, double-buffered K/V)
    attn_tc<<<dim3(8, 32), 256, ATTN_SMEM>>>(sinks);

    // Output projection
    out_gemm<<<dim3(16, 16), 256, GEMM_SMEM>>>(out);
}

// round 10
// speedup vs baseline: 4.1016x; 1.0428x over previous
#include <cuda_runtime.h>
#include <cuda_bf16.h>
#include <math.h>
#include <stdint.h>

// Problem constants
constexpr int SEQ  = 2048;
constexpr int DM   = 2048;
constexpr int NH   = 16;
constexpr int NKV  = 4;
constexpr int HD   = 128;
constexpr int WIN  = 1024;
constexpr int KVD  = NKV * HD;   // 512
constexpr float CLIPV = 8.0f;
constexpr float SCALE_F = 0.08838834764831845f; // 1/sqrt(128)

// ---------------------------------------------------------------------------
// Static scratch (no allocations allowed)
// ---------------------------------------------------------------------------
__device__ __nv_bfloat16 g_xh[SEQ * DM],  g_xl[SEQ * DM];
__device__ __nv_bfloat16 g_wqh[DM * DM],  g_wql[DM * DM];
__device__ __nv_bfloat16 g_wkh[KVD * DM], g_wkl[KVD * DM];
__device__ __nv_bfloat16 g_wvh[KVD * DM], g_wvl[KVD * DM];
__device__ __nv_bfloat16 g_woh[DM * DM],  g_wol[DM * DM];
__device__ __nv_bfloat16 g_ah[SEQ * DM],  g_al[SEQ * DM];      // attn out hi/lo
__device__ __nv_bfloat16 g_qnh[SEQ * DM], g_qnl[SEQ * DM];     // q normed/roped hi/lo
__device__ __nv_bfloat16 g_knh[SEQ * KVD], g_knl[SEQ * KVD];   // k normed/roped hi/lo
__device__ __nv_bfloat16 g_vnh[SEQ * KVD], g_vnl[SEQ * KVD];   // v hi/lo
__device__ float g_cos[SEQ * 64], g_sin[SEQ * 64];             // rope tables

// ---------------------------------------------------------------------------
// PTX helpers (sm_80+ instruction set — ptxas here targets plain sm_103)
// ---------------------------------------------------------------------------
__device__ __forceinline__ uint32_t smem_u32(const void* p) {
    uint32_t a;
    asm("{ .reg .u64 t; cvta.to.shared.u64 t, %1; cvt.u32.u64 %0, t; }"
        : "=r"(a) : "l"(p));
    return a;
}

__device__ __forceinline__ void cp_async16(uint32_t sp, const void* gp) {
    asm volatile("cp.async.cg.shared.global [%0], [%1], 16;"
                 :: "r"(sp), "l"(gp) : "memory");
}
__device__ __forceinline__ void cp_commit() {
    asm volatile("cp.async.commit_group;" ::: "memory");
}
template <int N>
__device__ __forceinline__ void cp_wait() {
    asm volatile("cp.async.wait_group %0;" :: "n"(N) : "memory");
}

__device__ __forceinline__ void ldmatrix_x4(uint32_t* r, uint32_t addr) {
    asm volatile("ldmatrix.sync.aligned.m8n8.x4.shared.b16 {%0,%1,%2,%3}, [%4];"
                 : "=r"(r[0]), "=r"(r[1]), "=r"(r[2]), "=r"(r[3]) : "r"(addr));
}
__device__ __forceinline__ void ldmatrix_x4_trans(uint32_t* r, uint32_t addr) {
    asm volatile("ldmatrix.sync.aligned.m8n8.x4.trans.shared.b16 {%0,%1,%2,%3}, [%4];"
                 : "=r"(r[0]), "=r"(r[1]), "=r"(r[2]), "=r"(r[3]) : "r"(addr));
}

__device__ __forceinline__ void mma_16816(float* c, const uint32_t* a, const uint32_t* b) {
    asm volatile(
        "mma.sync.aligned.m16n8k16.row.col.f32.bf16.bf16.f32 "
        "{%0,%1,%2,%3}, {%4,%5,%6,%7}, {%8,%9}, {%0,%1,%2,%3};"
        : "+f"(c[0]), "+f"(c[1]), "+f"(c[2]), "+f"(c[3])
        : "r"(a[0]), "r"(a[1]), "r"(a[2]), "r"(a[3]), "r"(b[0]), "r"(b[1]));
}

// ---------------------------------------------------------------------------
// Split fp32 -> (hi, lo) bf16
// ---------------------------------------------------------------------------
__device__ __forceinline__ void split_step(const float* __restrict__ x,
                                           __nv_bfloat16* __restrict__ hi,
                                           __nv_bfloat16* __restrict__ lo, int i) {
    float4 v = ((const float4*)x)[i];
    __nv_bfloat16 h0 = __float2bfloat16(v.x);
    __nv_bfloat16 h1 = __float2bfloat16(v.y);
    __nv_bfloat16 h2 = __float2bfloat16(v.z);
    __nv_bfloat16 h3 = __float2bfloat16(v.w);
    __nv_bfloat16 l0 = __float2bfloat16(v.x - __bfloat162float(h0));
    __nv_bfloat16 l1 = __float2bfloat16(v.y - __bfloat162float(h1));
    __nv_bfloat16 l2 = __float2bfloat16(v.z - __bfloat162float(h2));
    __nv_bfloat16 l3 = __float2bfloat16(v.w - __bfloat162float(h3));
    __nv_bfloat162 hp0 = __halves2bfloat162(h0, h1);
    __nv_bfloat162 hp1 = __halves2bfloat162(h2, h3);
    __nv_bfloat162 lp0 = __halves2bfloat162(l0, l1);
    __nv_bfloat162 lp1 = __halves2bfloat162(l2, l3);
    uint2 hv, lv;
    hv.x = *(uint32_t*)&hp0; hv.y = *(uint32_t*)&hp1;
    lv.x = *(uint32_t*)&lp0; lv.y = *(uint32_t*)&lp1;
    ((uint2*)hi)[i] = hv;
    ((uint2*)lo)[i] = lv;
}

__global__ void split_x_kernel(const float* __restrict__ x) {
    int i = blockIdx.x * 256 + threadIdx.x;   // 4096 blocks, n4 = 1048576
    split_step(x, g_xh, g_xl, i);
}

// All four weight splits in one launch. grid = 10240 blocks.
__global__ void split_w_kernel(const float* __restrict__ wq, const float* __restrict__ wk,
                               const float* __restrict__ wv, const float* __restrict__ wo) {
    int b = blockIdx.x;
    if (b < 4096) {
        split_step(wq, g_wqh, g_wql, b * 256 + threadIdx.x);
    } else if (b < 5120) {
        split_step(wk, g_wkh, g_wkl, (b - 4096) * 256 + threadIdx.x);
    } else if (b < 6144) {
        split_step(wv, g_wvh, g_wvl, (b - 5120) * 256 + threadIdx.x);
    } else {
        split_step(wo, g_woh, g_wol, (b - 6144) * 256 + threadIdx.x);
    }
}

// Rope tables (input-independent). grid = SEQ, 64 threads.
__global__ void rope_tab_kernel() {
    const int s = blockIdx.x, d = threadIdx.x;
    float inv = powf(500000.0f, -(float)d * (1.0f / 64.0f));
    float sn, cs;
    sincosf((float)s * inv, &sn, &cs);
    g_cos[s * 64 + d] = cs;
    g_sin[s * 64 + d] = sn;
}

// ---------------------------------------------------------------------------
// GEMM core: acc = A @ B^T for one 128x128 tile, 3 split MMAs per chunk.
// BK=32, 2-stage cp.async pipeline, 256 threads. A/B pointers pre-offset.
// ---------------------------------------------------------------------------
constexpr int LDSROW = 40;
constexpr int TILE_B = 128 * LDSROW * 2;    // 10240 B
constexpr int CHUNK_B = 4 * TILE_B;         // 40960 B per stage
constexpr int GEMM_SMEM = 2 * CHUNK_B;      // 81920 B

__device__ __forceinline__ void gemm_core(
    const __nv_bfloat16* __restrict__ Ah, const __nv_bfloat16* __restrict__ Al,
    const __nv_bfloat16* __restrict__ Bh, const __nv_bfloat16* __restrict__ Bl,
    int K, float acc[4][4][4], char* dsm) {
    const uint32_t sm0 = smem_u32(dsm);
    const int tid = threadIdx.x;
    const int wid = tid >> 5;
    const int lane = tid & 31;
    const int warp_m = wid & 1;
    const int warp_n = wid >> 1;
    const int NC = K >> 5;

    #pragma unroll
    for (int i = 0; i < 4; i++)
        #pragma unroll
        for (int j = 0; j < 4; j++)
            #pragma unroll
            for (int t = 0; t < 4; t++) acc[i][j][t] = 0.0f;

    auto load_chunk = [&](int c, int s) {
        const int k0 = c << 5;
        const uint32_t b = sm0 + s * CHUNK_B;
        #pragma unroll
        for (int t = 0; t < 2; t++) {
            int idx = tid + t * 256;
            int r = idx >> 2, g = idx & 3;
            uint32_t off = (uint32_t)(r * LDSROW + g * 8) * 2;
            const size_t ga = (size_t)r * K + k0 + g * 8;
            cp_async16(b + off, Ah + ga);
            cp_async16(b + TILE_B + off, Al + ga);
            cp_async16(b + 2 * TILE_B + off, Bh + ga);
            cp_async16(b + 3 * TILE_B + off, Bl + ga);
        }
    };

    load_chunk(0, 0);
    cp_commit();

    for (int c = 0; c < NC; c++) {
        if (c + 1 < NC) {
            load_chunk(c + 1, (c + 1) & 1);
            cp_commit();
            cp_wait<1>();
        } else {
            cp_wait<0>();
        }
        __syncthreads();

        const uint32_t b = sm0 + (c & 1) * CHUNK_B;
        #pragma unroll
        for (int ks = 0; ks < 2; ks++) {
            const int kc = ks * 16;
            uint32_t ah4[4][4], al4[4][4], bh[4][2], bl[4][2];
            #pragma unroll
            for (int im = 0; im < 4; im++) {
                int row = warp_m * 64 + im * 16 + (lane & 15);
                int col = kc + ((lane >> 4) << 3);
                ldmatrix_x4(ah4[im], b + (uint32_t)(row * LDSROW + col) * 2);
            }
            #pragma unroll
            for (int ib = 0; ib < 2; ib++) {
                int n = warp_n * 32 + ib * 16 + (lane & 7) + ((lane >> 4) << 3);
                int col = kc + (lane & 8);
                uint32_t r4[4];
                ldmatrix_x4(r4, b + 2 * TILE_B + (uint32_t)(n * LDSROW + col) * 2);
                bh[ib * 2][0] = r4[0]; bh[ib * 2][1] = r4[1];
                bh[ib * 2 + 1][0] = r4[2]; bh[ib * 2 + 1][1] = r4[3];
                ldmatrix_x4(r4, b + 3 * TILE_B + (uint32_t)(n * LDSROW + col) * 2);
                bl[ib * 2][0] = r4[0]; bl[ib * 2][1] = r4[1];
                bl[ib * 2 + 1][0] = r4[2]; bl[ib * 2 + 1][1] = r4[3];
            }
            #pragma unroll
            for (int im = 0; im < 4; im++)
                #pragma unroll
                for (int in = 0; in < 4; in++)
                    mma_16816(acc[im][in], ah4[im], bh[in]);
            #pragma unroll
            for (int im = 0; im < 4; im++)
                #pragma unroll
                for (int in = 0; in < 4; in++)
                    mma_16816(acc[im][in], ah4[im], bl[in]);
            #pragma unroll
            for (int im = 0; im < 4; im++) {
                int row = warp_m * 64 + im * 16 + (lane & 15);
                int col = kc + ((lane >> 4) << 3);
                ldmatrix_x4(al4[im], b + TILE_B + (uint32_t)(row * LDSROW + col) * 2);
            }
            #pragma unroll
            for (int im = 0; im < 4; im++)
                #pragma unroll
                for (int in = 0; in < 4; in++)
                    mma_16816(acc[im][in], al4[im], bh[in]);
        }
        __syncthreads();
    }
}

// Epilogue: clip + RMSNorm + RoPE + split-bf16 write (one head per col-block).
__device__ __forceinline__ void epi_norm_rope(
    float acc[4][4][4], char* dsm, int row0, int col0, int LD,
    const float* __restrict__ w,
    __nv_bfloat16* __restrict__ dh, __nv_bfloat16* __restrict__ dl) {
    const int tid = threadIdx.x;
    const int wid = tid >> 5;
    const int lane = tid & 31;
    const int warp_m = wid & 1;
    const int warp_n = wid >> 1;
    float* xs = (float*)dsm;                 // [128][132]
    float* rs = xs + 128 * 132;              // [128][4]

    #pragma unroll
    for (int im = 0; im < 4; im++) {
        #pragma unroll
        for (int half = 0; half < 2; half++) {
            const int rl = warp_m * 64 + im * 16 + (lane >> 2) + half * 8;
            float ss = 0.0f;
            #pragma unroll
            for (int in = 0; in < 4; in++) {
                #pragma unroll
                for (int c = 0; c < 2; c++) {
                    float v = acc[im][in][half * 2 + c];
                    v = fminf(fmaxf(v, -CLIPV), CLIPV);
                    acc[im][in][half * 2 + c] = v;
                    xs[rl * 132 + warp_n * 32 + in * 8 + 2 * (lane & 3) + c] = v;
                    ss += v * v;
                }
            }
            ss += __shfl_xor_sync(0xffffffffu, ss, 1);
            ss += __shfl_xor_sync(0xffffffffu, ss, 2);
            if ((lane & 3) == 0) rs[rl * 4 + warp_n] = ss;
        }
    }
    __syncthreads();

    #pragma unroll
    for (int im = 0; im < 4; im++) {
        #pragma unroll
        for (int half = 0; half < 2; half++) {
            const int rl = warp_m * 64 + im * 16 + (lane >> 2) + half * 8;
            const int pos = row0 + rl;
            const float sum = rs[rl * 4] + rs[rl * 4 + 1] + rs[rl * 4 + 2] + rs[rl * 4 + 3];
            const float rsig = rsqrtf(sum * (1.0f / HD) + 1e-6f);
            #pragma unroll
            for (int in = 0; in < 4; in++) {
                const int col = warp_n * 32 + in * 8 + 2 * (lane & 3);
                float o[2];
                #pragma unroll
                for (int c = 0; c < 2; c++) {
                    const int cc = col + c;
                    const float xn = acc[im][in][half * 2 + c] * rsig * w[cc];
                    const float xp = xs[rl * 132 + (cc ^ 64)] * rsig * w[cc ^ 64];
                    const float cs = g_cos[pos * 64 + (cc & 63)];
                    const float sn = g_sin[pos * 64 + (cc & 63)];
                    o[c] = xn * cs + ((cc < 64) ? -xp : xp) * sn;
                }
                __nv_bfloat162 hp = __floats2bfloat162_rn(o[0], o[1]);
                __nv_bfloat162 lp = __floats2bfloat162_rn(o[0] - __low2float(hp),
                                                          o[1] - __high2float(hp));
                const size_t off = (size_t)pos * LD + col0 + col;
                *(__nv_bfloat162*)(dh + off) = hp;
                *(__nv_bfloat162*)(dl + off) = lp;
            }
        }
    }
}

// Epilogue: clip + split-bf16 write (V path).
__device__ __forceinline__ void epi_split(
    float acc[4][4][4], int row0, int col0, int LD,
    __nv_bfloat16* __restrict__ dh, __nv_bfloat16* __restrict__ dl) {
    const int tid = threadIdx.x;
    const int wid = tid >> 5;
    const int lane = tid & 31;
    const int warp_m = wid & 1;
    const int warp_n = wid >> 1;
    #pragma unroll
    for (int im = 0; im < 4; im++) {
        #pragma unroll
        for (int half = 0; half < 2; half++) {
            const int row = row0 + warp_m * 64 + im * 16 + (lane >> 2) + half * 8;
            #pragma unroll
            for (int in = 0; in < 4; in++) {
                const int col = warp_n * 32 + in * 8 + 2 * (lane & 3);
                float o[2];
                #pragma unroll
                for (int c = 0; c < 2; c++)
                    o[c] = fminf(fmaxf(acc[im][in][half * 2 + c], -CLIPV), CLIPV);
                __nv_bfloat162 hp = __floats2bfloat162_rn(o[0], o[1]);
                __nv_bfloat162 lp = __floats2bfloat162_rn(o[0] - __low2float(hp),
                                                          o[1] - __high2float(hp));
                const size_t off = (size_t)row * LD + col0 + col;
                *(__nv_bfloat162*)(dh + off) = hp;
                *(__nv_bfloat162*)(dl + off) = lp;
            }
        }
    }
}

// Fused Q/K/V projection + norm/rope/split epilogues.
// grid (24, 16): x 0-15 -> Q heads, 16-19 -> K heads, 20-23 -> V heads.
__global__ __launch_bounds__(256, 2) void qkv_gemm(const float* __restrict__ qnw,
                                                   const float* __restrict__ knw) {
    extern __shared__ char dsm[];
    const int cx = blockIdx.x;
    const int row0 = blockIdx.y << 7;
    float acc[4][4][4];
    if (cx < 16) {
        const size_t bo = (size_t)(cx << 7) * DM;
        gemm_core(g_xh + (size_t)row0 * DM, g_xl + (size_t)row0 * DM,
                  g_wqh + bo, g_wql + bo, DM, acc, dsm);
        epi_norm_rope(acc, dsm, row0, cx << 7, DM, qnw, g_qnh, g_qnl);
    } else if (cx < 20) {
        const size_t bo = (size_t)((cx - 16) << 7) * DM;
        gemm_core(g_xh + (size_t)row0 * DM, g_xl + (size_t)row0 * DM,
                  g_wkh + bo, g_wkl + bo, DM, acc, dsm);
        epi_norm_rope(acc, dsm, row0, (cx - 16) << 7, KVD, knw, g_knh, g_knl);
    } else {
        const size_t bo = (size_t)((cx - 20) << 7) * DM;
        gemm_core(g_xh + (size_t)row0 * DM, g_xl + (size_t)row0 * DM,
                  g_wvh + bo, g_wvl + bo, DM, acc, dsm);
        epi_split(acc, row0, (cx - 20) << 7, KVD, g_vnh, g_vnl);
    }
}

// Output projection: plain fp32 epilogue.
__global__ __launch_bounds__(256, 2) void out_gemm(float* __restrict__ out) {
    extern __shared__ char dsm[];
    const int row0 = blockIdx.y << 7;
    const int col0 = blockIdx.x << 7;
    float acc[4][4][4];
    gemm_core(g_ah + (size_t)row0 * DM, g_al + (size_t)row0 * DM,
              g_woh + (size_t)col0 * DM, g_wol + (size_t)col0 * DM, DM, acc, dsm);
    const int tid = threadIdx.x;
    const int wid = tid >> 5;
    const int lane = tid & 31;
    const int warp_m = wid & 1;
    const int warp_n = wid >> 1;
    #pragma unroll
    for (int im = 0; im < 4; im++) {
        const int row = row0 + warp_m * 64 + im * 16 + (lane >> 2);
        #pragma unroll
        for (int in = 0; in < 4; in++) {
            const int col = col0 + warp_n * 32 + in * 8 + 2 * (lane & 3);
            *(float2*)(out + (size_t)row * DM + col) =
                make_float2(acc[im][in][0], acc[im][in][1]);
            *(float2*)(out + (size_t)(row + 8) * DM + col) =
                make_float2(acc[im][in][2], acc[im][in][3]);
        }
    }
}

// ---------------------------------------------------------------------------
// Tensor-core flash attention: two GQA heads per CTA (shared K/V),
// double-buffered K/V prefetch, mask-free fast path on interior tiles.
// grid = (8 head-pairs, 32 qtiles rev), 256 threads.
// ---------------------------------------------------------------------------
constexpr int AST = 136;
constexpr int TILE_E = 64 * AST;
constexpr int ATTN_SMEM = 12 * TILE_E * 2;   // 208896 B

__global__ __launch_bounds__(256, 1) void attn_tc(const float* __restrict__ sinks) {
    extern __shared__ __nv_bfloat16 smb[];
    const int g = blockIdx.x;
    const int qt = 31 - (int)blockIdx.y;
    const int q0 = qt << 6;
    const int kvh = g >> 1;
    const int tid = threadIdx.x;
    const int wid = tid >> 5;
    const int lane = tid & 31;
    const int hsel = wid >> 2;
    const int wq = wid & 3;
    const int h = g * 2 + hsel;

    __nv_bfloat16* Qh = smb + hsel * 2 * TILE_E;
    __nv_bfloat16* Ql = Qh + TILE_E;

    for (int idx = tid; idx < 2048; idx += 256) {
        int hd = idx >> 10;
        int rem = idx & 1023;
        int r = rem >> 4, c = rem & 15;
        const size_t go = (size_t)(q0 + r) * DM + (g * 2 + hd) * HD + c * 8;
        cp_async16(smem_u32(smb + hd * 2 * TILE_E + r * AST + c * 8), g_qnh + go);
        cp_async16(smem_u32(smb + (hd * 2 + 1) * TILE_E + r * AST + c * 8), g_qnl + go);
    }
    cp_commit();

    auto load_kv = [&](int kt, int b) {
        const int k0 = kt << 6;
        __nv_bfloat16* Khp = smb + (4 + 2 * b) * TILE_E;
        __nv_bfloat16* Klp = Khp + TILE_E;
        __nv_bfloat16* Vhp = smb + (8 + 2 * b) * TILE_E;
        __nv_bfloat16* Vlp = Vhp + TILE_E;
        for (int idx = tid; idx < 1024; idx += 256) {
            int r = idx >> 4, c = idx & 15;
            const size_t go = (size_t)(k0 + r) * KVD + kvh * HD + c * 8;
            cp_async16(smem_u32(Khp + r * AST + c * 8), g_knh + go);
            cp_async16(smem_u32(Klp + r * AST + c * 8), g_knl + go);
            cp_async16(smem_u32(Vhp + r * AST + c * 8), g_vnh + go);
            cp_async16(smem_u32(Vlp + r * AST + c * 8), g_vnl + go);
        }
    };

    int lo = q0 - WIN + 1;
    if (lo < 0) lo = 0;
    const int kt_lo = lo >> 6;
    load_kv(kt_lo, 0);
    cp_commit();

    float m[2] = {-1e30f, -1e30f}, lsum[2] = {0.0f, 0.0f};
    float acc_o[16][4];
    #pragma unroll
    for (int n = 0; n < 16; n++)
        #pragma unroll
        for (int t = 0; t < 4; t++) acc_o[n][t] = 0.0f;

    const int r0 = lane >> 2;

    for (int kt = kt_lo; kt <= qt; kt++) {
        const int b = (kt - kt_lo) & 1;
        const int k0 = kt << 6;
        const bool need_mask = (kt == qt) || (k0 < lo);
        if (kt < qt) {
            load_kv(kt + 1, b ^ 1);
            cp_commit();
            cp_wait<1>();
        } else {
            cp_wait<0>();
        }
        __syncthreads();

        __nv_bfloat16* Kh = smb + (4 + 2 * b) * TILE_E;
        __nv_bfloat16* Kl = Kh + TILE_E;
        __nv_bfloat16* Vh = smb + (8 + 2 * b) * TILE_E;
        __nv_bfloat16* Vl = Vh + TILE_E;

        // ---- S = Q K^T (3 split passes) ----
        float acc_s[8][4];
        #pragma unroll
        for (int j = 0; j < 8; j++)
            #pragma unroll
            for (int t = 0; t < 4; t++) acc_s[j][t] = 0.0f;

        #pragma unroll
        for (int ks = 0; ks < 8; ks++) {
            uint32_t ah4[4], al4[4];
            const int qrow = wq * 16 + (lane & 15);
            const int qcol = ks * 16 + ((lane >> 4) << 3);
            ldmatrix_x4(ah4, smem_u32(Qh + qrow * AST + qcol));
            ldmatrix_x4(al4, smem_u32(Ql + qrow * AST + qcol));
            #pragma unroll
            for (int np = 0; np < 4; np++) {
                const int n = np * 16 + (lane & 7) + ((lane >> 4) << 3);
                const int col = ks * 16 + (lane & 8);
                uint32_t bh4[4], bl4[4];
                ldmatrix_x4(bh4, smem_u32(Kh + n * AST + col));
                ldmatrix_x4(bl4, smem_u32(Kl + n * AST + col));
                mma_16816(acc_s[2 * np],     ah4, bh4);
                mma_16816(acc_s[2 * np],     al4, bh4);
                mma_16816(acc_s[2 * np],     ah4, bl4);
                mma_16816(acc_s[2 * np + 1], ah4, bh4 + 2);
                mma_16816(acc_s[2 * np + 1], al4, bh4 + 2);
                mma_16816(acc_s[2 * np + 1], ah4, bl4 + 2);
            }
        }

        // ---- mask + online softmax ----
        #pragma unroll
        for (int half = 0; half < 2; half++) {
            const int qi = q0 + wq * 16 + r0 + half * 8;
            float rm = -1e30f;
            if (need_mask) {
                #pragma unroll
                for (int j = 0; j < 8; j++) {
                    #pragma unroll
                    for (int c = 0; c < 2; c++) {
                        const int ki = k0 + j * 8 + 2 * (lane & 3) + c;
                        float v = acc_s[j][half * 2 + c];
                        v = (ki <= qi && ki > qi - WIN) ? v * SCALE_F : -1e30f;
                        acc_s[j][half * 2 + c] = v;
                        rm = fmaxf(rm, v);
                    }
                }
            } else {
                #pragma unroll
                for (int j = 0; j < 8; j++) {
                    #pragma unroll
                    for (int c = 0; c < 2; c++) {
                        float v = acc_s[j][half * 2 + c] * SCALE_F;
                        acc_s[j][half * 2 + c] = v;
                        rm = fmaxf(rm, v);
                    }
                }
            }
            rm = fmaxf(rm, __shfl_xor_sync(0xffffffffu, rm, 1));
            rm = fmaxf(rm, __shfl_xor_sync(0xffffffffu, rm, 2));
            const float nm = fmaxf(m[half], rm);
            const float sc = __expf(m[half] - nm);
            float rs = 0.0f;
            #pragma unroll
            for (int j = 0; j < 8; j++) {
                #pragma unroll
                for (int c = 0; c < 2; c++) {
                    float v = acc_s[j][half * 2 + c];
                    float p = (v > -1e29f) ? __expf(v - nm) : 0.0f;
                    acc_s[j][half * 2 + c] = p;
                    rs += p;
                }
            }
            rs += __shfl_xor_sync(0xffffffffu, rs, 1);
            rs += __shfl_xor_sync(0xffffffffu, rs, 2);
            lsum[half] = lsum[half] * sc + rs;
            m[half] = nm;
            #pragma unroll
            for (int n = 0; n < 16; n++) {
                acc_o[n][half * 2]     *= sc;
                acc_o[n][half * 2 + 1] *= sc;
            }
        }

        // ---- repack P into A fragments (hi + lo) ----
        uint32_t aPh[4][4], aPl[4][4];
        #pragma unroll
        for (int kk = 0; kk < 4; kk++) {
            #pragma unroll
            for (int t = 0; t < 4; t++) {
                const int j = 2 * kk + (t >> 1);
                const int c0 = (t & 1) * 2;
                const float p0 = acc_s[j][c0], p1 = acc_s[j][c0 + 1];
                __nv_bfloat162 hp = __floats2bfloat162_rn(p0, p1);
                __nv_bfloat162 lp = __floats2bfloat162_rn(p0 - __low2float(hp),
                                                          p1 - __high2float(hp));
                aPh[kk][t] = *(uint32_t*)&hp;
                aPl[kk][t] = *(uint32_t*)&lp;
            }
        }

        // ---- O += P V (3 split passes) ----
        #pragma unroll
        for (int kk = 0; kk < 4; kk++) {
            const int vrow = kk * 16 + (lane & 15);
            const int vcol = (lane >> 4) << 3;
            #pragma unroll
            for (int np = 0; np < 8; np++) {
                uint32_t bh4[4], bl4[4];
                ldmatrix_x4_trans(bh4, smem_u32(Vh + vrow * AST + np * 16 + vcol));
                mma_16816(acc_o[2 * np],     aPh[kk], bh4);
                mma_16816(acc_o[2 * np + 1], aPh[kk], bh4 + 2);
                mma_16816(acc_o[2 * np],     aPl[kk], bh4);
                mma_16816(acc_o[2 * np + 1], aPl[kk], bh4 + 2);
                ldmatrix_x4_trans(bl4, smem_u32(Vl + vrow * AST + np * 16 + vcol));
                mma_16816(acc_o[2 * np],     aPh[kk], bl4);
                mma_16816(acc_o[2 * np + 1], aPh[kk], bl4 + 2);
            }
        }
        __syncthreads();
    }

    // ---- sink fold + write split-bf16 output ----
    const float snk = sinks[h];
    #pragma unroll
    for (int half = 0; half < 2; half++) {
        const float M = fmaxf(m[half], snk);
        const float denom = lsum[half] * __expf(m[half] - M) + __expf(snk - M);
        const float ns = __expf(m[half] - M) / denom;
        const int row = q0 + wq * 16 + r0 + half * 8;
        #pragma unroll
        for (int n = 0; n < 16; n++) {
            const float v0 = acc_o[n][half * 2] * ns;
            const float v1 = acc_o[n][half * 2 + 1] * ns;
            __nv_bfloat162 hp = __floats2bfloat162_rn(v0, v1);
            __nv_bfloat162 lp = __floats2bfloat162_rn(v0 - __low2float(hp),
                                                      v1 - __high2float(hp));
            const size_t off = (size_t)row * DM + h * HD + n * 8 + 2 * (lane & 3);
            *(__nv_bfloat162*)(g_ah + off) = hp;
            *(__nv_bfloat162*)(g_al + off) = lp;
        }
    }
}

// ---------------------------------------------------------------------------
// Launch. Order matters: attn_tc at my-launch idx 4 gets ncu-profiled.
// ---------------------------------------------------------------------------
extern "C" void kernel_launch(void* const* d_in, const int* in_sizes, int n_in,
                              void* d_out, int out_size) {
    const float* x     = (const float*)d_in[0];
    const float* w_q   = (const float*)d_in[1];
    const float* w_k   = (const float*)d_in[2];
    const float* w_v   = (const float*)d_in[3];
    const float* w_out = (const float*)d_in[4];
    const float* qnw   = (const float*)d_in[5];
    const float* knw   = (const float*)d_in[6];
    const float* sinks = (const float*)d_in[7];
    float* out = (float*)d_out;

    cudaFuncSetAttribute(qkv_gemm, cudaFuncAttributeMaxDynamicSharedMemorySize, GEMM_SMEM);
    cudaFuncSetAttribute(out_gemm, cudaFuncAttributeMaxDynamicSharedMemorySize, GEMM_SMEM);
    cudaFuncSetAttribute(attn_tc,  cudaFuncAttributeMaxDynamicSharedMemorySize, ATTN_SMEM);

    // 0: weight splits (one launch)
    split_w_kernel<<<10240, 256>>>(w_q, w_k, w_v, w_out);
    // 1: x split
    split_x_kernel<<<4096, 256>>>(x);
    // 2: rope tables
    rope_tab_kernel<<<SEQ, 64>>>();
    // 3: fused Q/K/V projection + clip + RMSNorm + RoPE + split epilogues
    qkv_gemm<<<dim3(24, 16), 256, GEMM_SMEM>>>(qnw, knw);
    // 4: windowed flash attention + sink  (profiled slot)
    attn_tc<<<dim3(8, 32), 256, ATTN_SMEM>>>(sinks);
    // 5: output projection
    out_gemm<<<dim3(16, 16), 256, GEMM_SMEM>>>(out);
}